// round 1
// baseline (speedup 1.0000x reference)
#include <cuda_runtime.h>
#include <cuda_bf16.h>
#include <math.h>

// Problem constants
#define B_    2
#define T_    2048
#define C_    1024
#define H_    16
#define D_    64
#define DSTD_ 60
#define M_    (B_*T_)   // 4096 rows

// Scratch (no cudaMalloc allowed) — 64 MB total
__device__ float g_Q[B_*H_*T_*D_];   // [B*H, T, D]
__device__ float g_K[B_*H_*T_*D_];
__device__ float g_V[B_*H_*T_*D_];
__device__ float g_Y[M_*C_];         // [B*T, C]

__device__ __forceinline__ float sigmoidf_(float v) { return 1.0f / (1.0f + __expf(-v)); }

// ---------------------------------------------------------------------------
// SGEMM NT: C[m,n] = sum_k A[m,k] * B[n,k]
// 128x128 block tile, BK=16, 256 threads, 8x8 per-thread microtile.
// mode 0: A = x, epilogue scatters q/k/v into g_Q/g_K/g_V with head scaling
// mode 1: A = g_Y, epilogue writes plain fp32 to Cout
// ---------------------------------------------------------------------------
__global__ __launch_bounds__(256) void sgemm_kernel(
    const float* __restrict__ A, const float* __restrict__ Bm, float* __restrict__ Cout,
    int Mdim, int Ndim, int Kdim, int mode,
    const float* __restrict__ w_std, const float* __restrict__ w_rec,
    const float* __restrict__ skip_std, const float* __restrict__ skip_low)
{
    __shared__ float As[16][128];
    __shared__ float Bs[16][128];

    const float* Ap = (mode == 1) ? g_Y : A;

    int tid = threadIdx.x;
    int tx = tid & 15, ty = tid >> 4;
    int m0 = blockIdx.y * 128;
    int n0 = blockIdx.x * 128;

    float acc[8][8];
#pragma unroll
    for (int i = 0; i < 8; i++)
#pragma unroll
        for (int j = 0; j < 8; j++) acc[i][j] = 0.0f;

    for (int k0 = 0; k0 < Kdim; k0 += 16) {
#pragma unroll
        for (int p = 0; p < 2; p++) {
            int f = tid + p * 256;          // 0..511
            int row = f >> 2;               // 0..127
            int c4 = (f & 3) << 2;          // 0,4,8,12
            float4 va = *(const float4*)&Ap[(size_t)(m0 + row) * Kdim + k0 + c4];
            As[c4 + 0][row] = va.x; As[c4 + 1][row] = va.y;
            As[c4 + 2][row] = va.z; As[c4 + 3][row] = va.w;
            float4 vb = *(const float4*)&Bm[(size_t)(n0 + row) * Kdim + k0 + c4];
            Bs[c4 + 0][row] = vb.x; Bs[c4 + 1][row] = vb.y;
            Bs[c4 + 2][row] = vb.z; Bs[c4 + 3][row] = vb.w;
        }
        __syncthreads();

#pragma unroll
        for (int kk = 0; kk < 16; kk++) {
            float a[8], b[8];
            *(float4*)&a[0] = *(const float4*)&As[kk][ty * 8];
            *(float4*)&a[4] = *(const float4*)&As[kk][ty * 8 + 4];
            *(float4*)&b[0] = *(const float4*)&Bs[kk][tx * 8];
            *(float4*)&b[4] = *(const float4*)&Bs[kk][tx * 8 + 4];
#pragma unroll
            for (int i = 0; i < 8; i++)
#pragma unroll
                for (int j = 0; j < 8; j++)
                    acc[i][j] = fmaf(a[i], b[j], acc[i][j]);
        }
        __syncthreads();
    }

    if (mode == 1) {
        // plain write (output projection result)
#pragma unroll
        for (int i = 0; i < 8; i++) {
            int m = m0 + ty * 8 + i;
            float4 v0 = make_float4(acc[i][0], acc[i][1], acc[i][2], acc[i][3]);
            float4 v1 = make_float4(acc[i][4], acc[i][5], acc[i][6], acc[i][7]);
            *(float4*)&Cout[(size_t)m * Ndim + n0 + tx * 8]     = v0;
            *(float4*)&Cout[(size_t)m * Ndim + n0 + tx * 8 + 4] = v1;
        }
    } else {
        // scatter into Q/K/V with per-head scaling. A thread's 8 columns are
        // consecutive and never cross a head (64) or section (1024) boundary.
        int nbase = n0 + tx * 8;
        int sec = nbase / C_;           // 0=q, 1=k, 2=v
        int f = nbase % C_;
        int h = f >> 6;
        int dbase = f & 63;
        float gstd = 1.0f, grec = 1.0f;
        if (sec < 2) {
            float ss = sigmoidf_(skip_std[0]);
            float sl = sigmoidf_(skip_low[0]);
            // fold D^-1/4 so scores = Q'.K' directly (0.25 power of 1/sqrt(64))
            gstd = sqrtf(fmaxf(w_std[h] * ss, 1e-8f)) * 0.35355339059327373f;
            grec = sqrtf(fmaxf(w_rec[h] * sl, 1e-8f)) * 0.35355339059327373f;
        }
        float* dst = (sec == 0) ? g_Q : (sec == 1) ? g_K : g_V;
#pragma unroll
        for (int i = 0; i < 8; i++) {
            int m = m0 + ty * 8 + i;
            int b = m >> 11;                 // /T_
            int t = m & (T_ - 1);
            size_t base = (((size_t)(b * H_ + h)) * T_ + t) * D_;
#pragma unroll
            for (int j = 0; j < 8; j++) {
                int d = dbase + j;
                float val = acc[i][j];
                if (sec < 2) val *= (d < DSTD_) ? gstd : grec;
                dst[base + d] = val;
            }
        }
    }
}

// ---------------------------------------------------------------------------
// Fused causal flash attention (fp32) + reciprocal mix.
// Block: 64 queries x full D=64, 256 threads (16x16), 4x4 microtiles.
// Grid: (T/64 q-tiles, B*H). Only kt <= qt KV tiles are visited (causal).
// ---------------------------------------------------------------------------
#define PAD_ 68   // 68 floats per row: 16B-aligned rows, stride%32 = 4 (mild conflicts)

__global__ __launch_bounds__(256) void attn_kernel(const float* __restrict__ rwr_alpha)
{
    extern __shared__ float sm[];
    float* Qs = sm;                 // 64 x PAD_
    float* Ks = sm + 64 * PAD_;
    float* Vs = sm + 2 * 64 * PAD_;
    float* Ps = sm + 3 * 64 * PAD_;

    int qt = blockIdx.x;
    int bh = blockIdx.y;
    int q0 = qt * 64;
    int tid = threadIdx.x;
    int tx = tid & 15, ty = tid >> 4;

    const float* Qg = g_Q + (size_t)bh * (T_ * D_);
    const float* Kg = g_K + (size_t)bh * (T_ * D_);
    const float* Vg = g_V + (size_t)bh * (T_ * D_);

    // load Q tile: 64x64 floats = 1024 float4, 4 per thread
#pragma unroll
    for (int p = 0; p < 4; p++) {
        int f = tid + p * 256;
        int r = f >> 4;
        int c = (f & 15) * 4;
        *(float4*)&Qs[r * PAD_ + c] = *(const float4*)&Qg[(size_t)(q0 + r) * D_ + c];
    }

    float Oacc[4][4];
    float m_i[4], l_i[4];
#pragma unroll
    for (int i = 0; i < 4; i++) {
        m_i[i] = -1e30f; l_i[i] = 0.0f;
#pragma unroll
        for (int j = 0; j < 4; j++) Oacc[i][j] = 0.0f;
    }

    for (int kt = 0; kt <= qt; kt++) {
        int k0 = kt * 64;
        __syncthreads();   // previous iteration's Ps/Vs reads done before overwrite
#pragma unroll
        for (int p = 0; p < 4; p++) {
            int f = tid + p * 256;
            int r = f >> 4;
            int c = (f & 15) * 4;
            *(float4*)&Ks[r * PAD_ + c] = *(const float4*)&Kg[(size_t)(k0 + r) * D_ + c];
            *(float4*)&Vs[r * PAD_ + c] = *(const float4*)&Vg[(size_t)(k0 + r) * D_ + c];
        }
        __syncthreads();

        // S = Q . K^T  (D^-1/4 already folded into Q and K)
        float S[4][4];
#pragma unroll
        for (int i = 0; i < 4; i++)
#pragma unroll
            for (int c = 0; c < 4; c++) S[i][c] = 0.0f;

#pragma unroll
        for (int kk = 0; kk < 64; kk += 4) {
            float qm[4][4], km[4][4];
#pragma unroll
            for (int i = 0; i < 4; i++) {
                float4 t4 = *(const float4*)&Qs[(ty * 4 + i) * PAD_ + kk];
                qm[i][0] = t4.x; qm[i][1] = t4.y; qm[i][2] = t4.z; qm[i][3] = t4.w;
            }
#pragma unroll
            for (int c = 0; c < 4; c++) {
                float4 t4 = *(const float4*)&Ks[(tx * 4 + c) * PAD_ + kk];
                km[c][0] = t4.x; km[c][1] = t4.y; km[c][2] = t4.z; km[c][3] = t4.w;
            }
#pragma unroll
            for (int i = 0; i < 4; i++)
#pragma unroll
                for (int c = 0; c < 4; c++)
#pragma unroll
                    for (int u = 0; u < 4; u++)
                        S[i][c] = fmaf(qm[i][u], km[c][u], S[i][c]);
        }

        // causal mask on the diagonal tile
        if (kt == qt) {
#pragma unroll
            for (int i = 0; i < 4; i++)
#pragma unroll
                for (int c = 0; c < 4; c++)
                    if (tx * 4 + c > ty * 4 + i) S[i][c] = -1e30f;
        }

        // online softmax update (row stats replicated across the 16-lane group)
#pragma unroll
        for (int i = 0; i < 4; i++) {
            float rmax = fmaxf(fmaxf(S[i][0], S[i][1]), fmaxf(S[i][2], S[i][3]));
            rmax = fmaxf(rmax, __shfl_xor_sync(0xffffffffu, rmax, 1));
            rmax = fmaxf(rmax, __shfl_xor_sync(0xffffffffu, rmax, 2));
            rmax = fmaxf(rmax, __shfl_xor_sync(0xffffffffu, rmax, 4));
            rmax = fmaxf(rmax, __shfl_xor_sync(0xffffffffu, rmax, 8));
            float mnew = fmaxf(m_i[i], rmax);
            float corr = __expf(m_i[i] - mnew);
            float rsum = 0.0f;
#pragma unroll
            for (int c = 0; c < 4; c++) {
                S[i][c] = __expf(S[i][c] - mnew);
                rsum += S[i][c];
            }
            rsum += __shfl_xor_sync(0xffffffffu, rsum, 1);
            rsum += __shfl_xor_sync(0xffffffffu, rsum, 2);
            rsum += __shfl_xor_sync(0xffffffffu, rsum, 4);
            rsum += __shfl_xor_sync(0xffffffffu, rsum, 8);
            l_i[i] = l_i[i] * corr + rsum;
            m_i[i] = mnew;
#pragma unroll
            for (int j = 0; j < 4; j++) Oacc[i][j] *= corr;
            *(float4*)&Ps[(ty * 4 + i) * PAD_ + tx * 4] =
                make_float4(S[i][0], S[i][1], S[i][2], S[i][3]);
        }
        __syncthreads();

        // O += P . V
#pragma unroll
        for (int kk = 0; kk < 64; kk += 4) {
            float pm[4][4], vm[4][4];
#pragma unroll
            for (int i = 0; i < 4; i++) {
                float4 t4 = *(const float4*)&Ps[(ty * 4 + i) * PAD_ + kk];
                pm[i][0] = t4.x; pm[i][1] = t4.y; pm[i][2] = t4.z; pm[i][3] = t4.w;
            }
#pragma unroll
            for (int u = 0; u < 4; u++) {
                float4 t4 = *(const float4*)&Vs[(kk + u) * PAD_ + tx * 4];
                vm[u][0] = t4.x; vm[u][1] = t4.y; vm[u][2] = t4.z; vm[u][3] = t4.w;
            }
#pragma unroll
            for (int i = 0; i < 4; i++)
#pragma unroll
                for (int j = 0; j < 4; j++)
#pragma unroll
                    for (int u = 0; u < 4; u++)
                        Oacc[i][j] = fmaf(pm[i][u], vm[u][j], Oacc[i][j]);
        }
    }

    // epilogue: normalize, reciprocal mix with V at query positions, write y[bt, c]
    int h = bh & (H_ - 1);
    int b = bh >> 4;
    float alpha = fminf(fmaxf(rwr_alpha[h], 0.0f), 0.5f);
    float one_minus = 1.0f - alpha;
#pragma unroll
    for (int i = 0; i < 4; i++) {
        int q = q0 + ty * 4 + i;
        float inv = 1.0f / l_i[i];
        float4 v = *(const float4*)&Vg[(size_t)q * D_ + tx * 4];
        float4 y;
        y.x = one_minus * (Oacc[i][0] * inv) + alpha * v.x;
        y.y = one_minus * (Oacc[i][1] * inv) + alpha * v.y;
        y.z = one_minus * (Oacc[i][2] * inv) + alpha * v.z;
        y.w = one_minus * (Oacc[i][3] * inv) + alpha * v.w;
        *(float4*)&g_Y[((size_t)(b * T_ + q)) * C_ + h * D_ + tx * 4] = y;
    }
}

// ---------------------------------------------------------------------------
extern "C" void kernel_launch(void* const* d_in, const int* in_sizes, int n_in,
                              void* d_out, int out_size)
{
    const float* x         = (const float*)d_in[0];
    const float* W_attn    = (const float*)d_in[1];
    const float* W_proj    = (const float*)d_in[2];
    const float* w_std     = (const float*)d_in[3];
    const float* w_rec     = (const float*)d_in[4];
    const float* skip_std  = (const float*)d_in[5];
    const float* skip_low  = (const float*)d_in[6];
    const float* rwr_alpha = (const float*)d_in[7];
    float* out = (float*)d_out;

    dim3 blk(256);

    // 1. QKV GEMM: [4096,1024] x [3072,1024]^T -> scatter Q/K/V with scaling
    sgemm_kernel<<<dim3(3072 / 128, 4096 / 128), blk>>>(
        x, W_attn, nullptr, M_, 3 * C_, C_, 0, w_std, w_rec, skip_std, skip_low);

    // 2. Fused causal attention + reciprocal mix
    int smem = 4 * 64 * PAD_ * (int)sizeof(float);   // 69632 bytes
    cudaFuncSetAttribute(attn_kernel, cudaFuncAttributeMaxDynamicSharedMemorySize, smem);
    attn_kernel<<<dim3(T_ / 64, B_ * H_), blk, smem>>>(rwr_alpha);

    // 3. Output projection: [4096,1024] x [1024,1024]^T -> out
    sgemm_kernel<<<dim3(1024 / 128, 4096 / 128), blk>>>(
        nullptr, W_proj, out, M_, C_, C_, 1, nullptr, nullptr, nullptr, nullptr);
}

// round 3
// speedup vs baseline: 1.4577x; 1.4577x over previous
#include <cuda_runtime.h>
#include <cuda_bf16.h>
#include <cstdint>
#include <math.h>

// Problem constants
#define B_    2
#define T_    2048
#define C_    1024
#define H_    16
#define D_    64
#define DSTD_ 60
#define M_    (B_*T_)   // 4096 rows

// ---------------------------------------------------------------------------
// Scratch (__device__ globals; no allocation allowed)
// ---------------------------------------------------------------------------
__device__ float g_Q[B_*H_*T_*D_];   // [B*H, T, D]
__device__ float g_K[B_*H_*T_*D_];
__device__ float g_V[B_*H_*T_*D_];
__device__ float g_Y[M_*C_];         // [B*T, C]

// bf16 hi/lo split operands
__device__ __nv_bfloat16 g_x_hi[M_*C_],    g_x_lo[M_*C_];
__device__ __nv_bfloat16 g_wa_hi[3*C_*C_], g_wa_lo[3*C_*C_];
__device__ __nv_bfloat16 g_wp_hi[C_*C_],   g_wp_lo[C_*C_];
__device__ __nv_bfloat16 g_y_hi[M_*C_],    g_y_lo[M_*C_];

__device__ __forceinline__ float sigmoidf_(float v) { return 1.0f / (1.0f + __expf(-v)); }

__device__ __forceinline__ uint32_t smem_u32(const void* p) {
    return (uint32_t)__cvta_generic_to_shared(p);
}

// ---------------------------------------------------------------------------
// warp-mma helpers (baseline PTX ISA — safe for compute_103 target)
// ---------------------------------------------------------------------------
__device__ __forceinline__ void ldsm4(uint32_t* r, uint32_t addr) {
    asm volatile("ldmatrix.sync.aligned.m8n8.x4.shared.b16 {%0,%1,%2,%3}, [%4];"
        : "=r"(r[0]), "=r"(r[1]), "=r"(r[2]), "=r"(r[3]) : "r"(addr));
}

__device__ __forceinline__ void mma_bf16(float* c, const uint32_t* a, uint32_t b0, uint32_t b1) {
    asm volatile("mma.sync.aligned.m16n8k16.row.col.f32.bf16.bf16.f32 "
        "{%0,%1,%2,%3}, {%4,%5,%6,%7}, {%8,%9}, {%0,%1,%2,%3};"
        : "+f"(c[0]), "+f"(c[1]), "+f"(c[2]), "+f"(c[3])
        : "r"(a[0]), "r"(a[1]), "r"(a[2]), "r"(a[3]), "r"(b0), "r"(b1));
}

__device__ __forceinline__ void cp16(uint32_t saddr, const void* gaddr) {
    asm volatile("cp.async.cg.shared.global [%0], [%1], 16;" :: "r"(saddr), "l"(gaddr));
}

// ---------------------------------------------------------------------------
// fp32 -> bf16 hi/lo split (vectorized, 4 elems/thread)
// ---------------------------------------------------------------------------
__global__ __launch_bounds__(256) void split_kernel(
    const float4* __restrict__ src, uint2* __restrict__ hi, uint2* __restrict__ lo, int n4)
{
    int i = blockIdx.x * blockDim.x + threadIdx.x;
    if (i >= n4) return;
    float4 v = src[i];
    __nv_bfloat16 h0 = __float2bfloat16(v.x);
    __nv_bfloat16 h1 = __float2bfloat16(v.y);
    __nv_bfloat16 h2 = __float2bfloat16(v.z);
    __nv_bfloat16 h3 = __float2bfloat16(v.w);
    __nv_bfloat16 l0 = __float2bfloat16(v.x - __bfloat162float(h0));
    __nv_bfloat16 l1 = __float2bfloat16(v.y - __bfloat162float(h1));
    __nv_bfloat16 l2 = __float2bfloat16(v.z - __bfloat162float(h2));
    __nv_bfloat16 l3 = __float2bfloat16(v.w - __bfloat162float(h3));
    uint2 ho, loo;
    ho.x  = (uint32_t)__bfloat16_as_ushort(h0) | ((uint32_t)__bfloat16_as_ushort(h1) << 16);
    ho.y  = (uint32_t)__bfloat16_as_ushort(h2) | ((uint32_t)__bfloat16_as_ushort(h3) << 16);
    loo.x = (uint32_t)__bfloat16_as_ushort(l0) | ((uint32_t)__bfloat16_as_ushort(l1) << 16);
    loo.y = (uint32_t)__bfloat16_as_ushort(l2) | ((uint32_t)__bfloat16_as_ushort(l3) << 16);
    hi[i] = ho;
    lo[i] = loo;
}

// ---------------------------------------------------------------------------
// Split-bf16 warp-MMA GEMM (NT): C[m,n] = sum_k A[m,k]*B[n,k], ~fp32 accuracy.
// CTA 128x128, BK=32. 8 warps as 2(m) x 4(n) -> 64x32 per warp.
// SMEM rows padded to 80B (conflict-free ldmatrix at stride 20 words).
// Stage = {Ah, Al, Bh, Bl} tiles of 128 x 32 bf16 (10240 B each).
// mode 0: scatter q/k/v with head scaling; mode 1: plain fp32 write.
// ---------------------------------------------------------------------------
#define OP_BYTES    10240          // 128 rows * 80 B
#define STAGE_B     (4*OP_BYTES)   // 40960

__device__ __forceinline__ void load_op(
    uint32_t sdst, const __nv_bfloat16* __restrict__ src, int Kdim, int k0, int tid)
{
#pragma unroll
    for (int p = 0; p < 2; p++) {
        int idx = tid + p * 256;        // 0..511
        int row = idx >> 2;             // 0..127
        int c8  = (idx & 3) * 8;        // bf16 col
        cp16(sdst + row * 80 + c8 * 2, src + (size_t)row * Kdim + k0 + c8);
    }
}

__global__ void __launch_bounds__(256) gemm_mma_kernel(
    const __nv_bfloat16* __restrict__ Ahi, const __nv_bfloat16* __restrict__ Alo,
    const __nv_bfloat16* __restrict__ Bhi, const __nv_bfloat16* __restrict__ Blo,
    float* __restrict__ Cout, int Ndim, int Kdim, int mode,
    const float* __restrict__ w_std, const float* __restrict__ w_rec,
    const float* __restrict__ skip_std, const float* __restrict__ skip_low)
{
    extern __shared__ char smem[];
    const uint32_t sbase = smem_u32(smem);
    const int tid  = threadIdx.x;
    const int wid  = tid >> 5;
    const int lane = tid & 31;
    const int warp_m = wid >> 2;        // 0..1
    const int warp_n = wid & 3;         // 0..3

    const int m0 = blockIdx.y * 128;
    const int n0 = blockIdx.x * 128;

    // per-lane ldmatrix row/col offsets
    const int lr  = lane & 7, sel = lane >> 3;
    const int rowA = ((sel & 1) ? 8 : 0) + lr;
    const int kbA  = (sel & 2) ? 16 : 0;
    const int rowB = ((sel & 2) ? 8 : 0) + lr;
    const int kbB  = (sel & 1) ? 16 : 0;

    const uint32_t aoff = (uint32_t)((warp_m * 64 + rowA) * 80 + kbA);
    const uint32_t boff = (uint32_t)((warp_n * 32 + rowB) * 80 + kbB);

    const __nv_bfloat16* As_hi = Ahi + (size_t)m0 * Kdim;
    const __nv_bfloat16* As_lo = Alo + (size_t)m0 * Kdim;
    const __nv_bfloat16* Bs_hi = Bhi + (size_t)n0 * Kdim;
    const __nv_bfloat16* Bs_lo = Blo + (size_t)n0 * Kdim;

    float acc[4][4][4];
#pragma unroll
    for (int a = 0; a < 4; a++)
#pragma unroll
        for (int b = 0; b < 4; b++)
#pragma unroll
            for (int c = 0; c < 4; c++) acc[a][b][c] = 0.0f;

    const int nch = Kdim >> 5;          // BK=32

    // prologue: stage 0, chunk 0
    load_op(sbase,               As_hi, Kdim, 0, tid);
    load_op(sbase +   OP_BYTES,  As_lo, Kdim, 0, tid);
    load_op(sbase + 2*OP_BYTES,  Bs_hi, Kdim, 0, tid);
    load_op(sbase + 3*OP_BYTES,  Bs_lo, Kdim, 0, tid);
    asm volatile("cp.async.commit_group;" ::: "memory");

    for (int i = 0; i < nch; i++) {
        const int s = i & 1;
        if (i + 1 < nch) {
            const uint32_t st = sbase + (uint32_t)(s ^ 1) * STAGE_B;
            const int k0 = (i + 1) << 5;
            load_op(st,               As_hi, Kdim, k0, tid);
            load_op(st +   OP_BYTES,  As_lo, Kdim, k0, tid);
            load_op(st + 2*OP_BYTES,  Bs_hi, Kdim, k0, tid);
            load_op(st + 3*OP_BYTES,  Bs_lo, Kdim, k0, tid);
            asm volatile("cp.async.commit_group;" ::: "memory");
            asm volatile("cp.async.wait_group 1;" ::: "memory");
        } else {
            asm volatile("cp.async.wait_group 0;" ::: "memory");
        }
        __syncthreads();

        const uint32_t sb = sbase + (uint32_t)s * STAGE_B;
#pragma unroll
        for (int step = 0; step < 2; step++) {
            uint32_t ah[4][4], al[4][4], bh[2][4], bl[2][4];
            const uint32_t ks = (uint32_t)(step * 32);
#pragma unroll
            for (int mt = 0; mt < 4; mt++) {
                ldsm4(ah[mt], sb + aoff + (uint32_t)(mt * 1280) + ks);
                ldsm4(al[mt], sb + OP_BYTES + aoff + (uint32_t)(mt * 1280) + ks);
            }
#pragma unroll
            for (int np = 0; np < 2; np++) {
                ldsm4(bh[np], sb + 2*OP_BYTES + boff + (uint32_t)(np * 1280) + ks);
                ldsm4(bl[np], sb + 3*OP_BYTES + boff + (uint32_t)(np * 1280) + ks);
            }
#pragma unroll
            for (int mt = 0; mt < 4; mt++)
#pragma unroll
                for (int nt = 0; nt < 4; nt++) {
                    const int np = nt >> 1, hl = (nt & 1) * 2;
                    mma_bf16(acc[mt][nt], ah[mt], bh[np][hl], bh[np][hl + 1]);
                    mma_bf16(acc[mt][nt], ah[mt], bl[np][hl], bl[np][hl + 1]);
                    mma_bf16(acc[mt][nt], al[mt], bh[np][hl], bh[np][hl + 1]);
                }
        }
        __syncthreads();
    }

    // ----------------------------- epilogue --------------------------------
    const int lr4 = lane >> 2;          // row within 8
    const int lc2 = (lane & 3) * 2;     // col pair

    if (mode == 0) {
        const int nb  = n0 + warp_n * 32;       // 32-aligned: sec & head constant
        const int sec = nb >> 10;               // 0=q 1=k 2=v
        const int f   = nb & 1023;
        const int h   = f >> 6;
        float gstd = 1.0f, grec = 1.0f;
        if (sec < 2) {
            const float ss = sigmoidf_(skip_std[0]);
            const float sl = sigmoidf_(skip_low[0]);
            gstd = sqrtf(fmaxf(w_std[h] * ss, 1e-8f)) * 0.35355339059327373f;
            grec = sqrtf(fmaxf(w_rec[h] * sl, 1e-8f)) * 0.35355339059327373f;
        }
        float* dst = (sec == 0) ? g_Q : (sec == 1) ? g_K : g_V;
#pragma unroll
        for (int mt = 0; mt < 4; mt++) {
            const int r0 = m0 + warp_m * 64 + mt * 16 + lr4;
#pragma unroll
            for (int half = 0; half < 2; half++) {
                const int m = r0 + half * 8;
                const int b = m >> 11;
                const int t = m & (T_ - 1);
                const size_t base = (((size_t)(b * H_ + h)) * T_ + t) * D_;
#pragma unroll
                for (int nt = 0; nt < 4; nt++) {
                    const int d = (f & 63) + nt * 8 + lc2;
                    const float s0v = (sec < 2) ? ((d     < DSTD_) ? gstd : grec) : 1.0f;
                    const float s1v = (sec < 2) ? ((d + 1 < DSTD_) ? gstd : grec) : 1.0f;
                    float2 o;
                    o.x = acc[mt][nt][half * 2 + 0] * s0v;
                    o.y = acc[mt][nt][half * 2 + 1] * s1v;
                    *(float2*)&dst[base + d] = o;
                }
            }
        }
    } else {
#pragma unroll
        for (int mt = 0; mt < 4; mt++) {
            const int r0 = m0 + warp_m * 64 + mt * 16 + lr4;
#pragma unroll
            for (int half = 0; half < 2; half++) {
                const int m = r0 + half * 8;
#pragma unroll
                for (int nt = 0; nt < 4; nt++) {
                    const int col = n0 + warp_n * 32 + nt * 8 + lc2;
                    float2 o;
                    o.x = acc[mt][nt][half * 2 + 0];
                    o.y = acc[mt][nt][half * 2 + 1];
                    *(float2*)&Cout[(size_t)m * Ndim + col] = o;
                }
            }
        }
    }
}

// ---------------------------------------------------------------------------
// Fused causal flash attention (fp32) + reciprocal mix. (unchanged)
// ---------------------------------------------------------------------------
#define PAD_ 68

__global__ __launch_bounds__(256) void attn_kernel(const float* __restrict__ rwr_alpha)
{
    extern __shared__ float sm[];
    float* Qs = sm;
    float* Ks = sm + 64 * PAD_;
    float* Vs = sm + 2 * 64 * PAD_;
    float* Ps = sm + 3 * 64 * PAD_;

    int qt = blockIdx.x;
    int bh = blockIdx.y;
    int q0 = qt * 64;
    int tid = threadIdx.x;
    int tx = tid & 15, ty = tid >> 4;

    const float* Qg = g_Q + (size_t)bh * (T_ * D_);
    const float* Kg = g_K + (size_t)bh * (T_ * D_);
    const float* Vg = g_V + (size_t)bh * (T_ * D_);

#pragma unroll
    for (int p = 0; p < 4; p++) {
        int f = tid + p * 256;
        int r = f >> 4;
        int c = (f & 15) * 4;
        *(float4*)&Qs[r * PAD_ + c] = *(const float4*)&Qg[(size_t)(q0 + r) * D_ + c];
    }

    float Oacc[4][4];
    float m_i[4], l_i[4];
#pragma unroll
    for (int i = 0; i < 4; i++) {
        m_i[i] = -1e30f; l_i[i] = 0.0f;
#pragma unroll
        for (int j = 0; j < 4; j++) Oacc[i][j] = 0.0f;
    }

    for (int kt = 0; kt <= qt; kt++) {
        int k0 = kt * 64;
        __syncthreads();
#pragma unroll
        for (int p = 0; p < 4; p++) {
            int f = tid + p * 256;
            int r = f >> 4;
            int c = (f & 15) * 4;
            *(float4*)&Ks[r * PAD_ + c] = *(const float4*)&Kg[(size_t)(k0 + r) * D_ + c];
            *(float4*)&Vs[r * PAD_ + c] = *(const float4*)&Vg[(size_t)(k0 + r) * D_ + c];
        }
        __syncthreads();

        float S[4][4];
#pragma unroll
        for (int i = 0; i < 4; i++)
#pragma unroll
            for (int c = 0; c < 4; c++) S[i][c] = 0.0f;

#pragma unroll
        for (int kk = 0; kk < 64; kk += 4) {
            float qm[4][4], km[4][4];
#pragma unroll
            for (int i = 0; i < 4; i++) {
                float4 t4 = *(const float4*)&Qs[(ty * 4 + i) * PAD_ + kk];
                qm[i][0] = t4.x; qm[i][1] = t4.y; qm[i][2] = t4.z; qm[i][3] = t4.w;
            }
#pragma unroll
            for (int c = 0; c < 4; c++) {
                float4 t4 = *(const float4*)&Ks[(tx * 4 + c) * PAD_ + kk];
                km[c][0] = t4.x; km[c][1] = t4.y; km[c][2] = t4.z; km[c][3] = t4.w;
            }
#pragma unroll
            for (int i = 0; i < 4; i++)
#pragma unroll
                for (int c = 0; c < 4; c++)
#pragma unroll
                    for (int u = 0; u < 4; u++)
                        S[i][c] = fmaf(qm[i][u], km[c][u], S[i][c]);
        }

        if (kt == qt) {
#pragma unroll
            for (int i = 0; i < 4; i++)
#pragma unroll
                for (int c = 0; c < 4; c++)
                    if (tx * 4 + c > ty * 4 + i) S[i][c] = -1e30f;
        }

#pragma unroll
        for (int i = 0; i < 4; i++) {
            float rmax = fmaxf(fmaxf(S[i][0], S[i][1]), fmaxf(S[i][2], S[i][3]));
            rmax = fmaxf(rmax, __shfl_xor_sync(0xffffffffu, rmax, 1));
            rmax = fmaxf(rmax, __shfl_xor_sync(0xffffffffu, rmax, 2));
            rmax = fmaxf(rmax, __shfl_xor_sync(0xffffffffu, rmax, 4));
            rmax = fmaxf(rmax, __shfl_xor_sync(0xffffffffu, rmax, 8));
            float mnew = fmaxf(m_i[i], rmax);
            float corr = __expf(m_i[i] - mnew);
            float rsum = 0.0f;
#pragma unroll
            for (int c = 0; c < 4; c++) {
                S[i][c] = __expf(S[i][c] - mnew);
                rsum += S[i][c];
            }
            rsum += __shfl_xor_sync(0xffffffffu, rsum, 1);
            rsum += __shfl_xor_sync(0xffffffffu, rsum, 2);
            rsum += __shfl_xor_sync(0xffffffffu, rsum, 4);
            rsum += __shfl_xor_sync(0xffffffffu, rsum, 8);
            l_i[i] = l_i[i] * corr + rsum;
            m_i[i] = mnew;
#pragma unroll
            for (int j = 0; j < 4; j++) Oacc[i][j] *= corr;
            *(float4*)&Ps[(ty * 4 + i) * PAD_ + tx * 4] =
                make_float4(S[i][0], S[i][1], S[i][2], S[i][3]);
        }
        __syncthreads();

#pragma unroll
        for (int kk = 0; kk < 64; kk += 4) {
            float pm[4][4], vm[4][4];
#pragma unroll
            for (int i = 0; i < 4; i++) {
                float4 t4 = *(const float4*)&Ps[(ty * 4 + i) * PAD_ + kk];
                pm[i][0] = t4.x; pm[i][1] = t4.y; pm[i][2] = t4.z; pm[i][3] = t4.w;
            }
#pragma unroll
            for (int u = 0; u < 4; u++) {
                float4 t4 = *(const float4*)&Vs[(kk + u) * PAD_ + tx * 4];
                vm[u][0] = t4.x; vm[u][1] = t4.y; vm[u][2] = t4.z; vm[u][3] = t4.w;
            }
#pragma unroll
            for (int i = 0; i < 4; i++)
#pragma unroll
                for (int j = 0; j < 4; j++)
#pragma unroll
                    for (int u = 0; u < 4; u++)
                        Oacc[i][j] = fmaf(pm[i][u], vm[u][j], Oacc[i][j]);
        }
    }

    int h = bh & (H_ - 1);
    int b = bh >> 4;
    float alpha = fminf(fmaxf(rwr_alpha[h], 0.0f), 0.5f);
    float one_minus = 1.0f - alpha;
#pragma unroll
    for (int i = 0; i < 4; i++) {
        int q = q0 + ty * 4 + i;
        float inv = 1.0f / l_i[i];
        float4 v = *(const float4*)&Vg[(size_t)q * D_ + tx * 4];
        float4 y;
        y.x = one_minus * (Oacc[i][0] * inv) + alpha * v.x;
        y.y = one_minus * (Oacc[i][1] * inv) + alpha * v.y;
        y.z = one_minus * (Oacc[i][2] * inv) + alpha * v.z;
        y.w = one_minus * (Oacc[i][3] * inv) + alpha * v.w;
        *(float4*)&g_Y[((size_t)(b * T_ + q)) * C_ + h * D_ + tx * 4] = y;
    }
}

// ---------------------------------------------------------------------------
extern "C" void kernel_launch(void* const* d_in, const int* in_sizes, int n_in,
                              void* d_out, int out_size)
{
    const float* x         = (const float*)d_in[0];
    const float* W_attn    = (const float*)d_in[1];
    const float* W_proj    = (const float*)d_in[2];
    const float* w_std     = (const float*)d_in[3];
    const float* w_rec     = (const float*)d_in[4];
    const float* skip_std  = (const float*)d_in[5];
    const float* skip_low  = (const float*)d_in[6];
    const float* rwr_alpha = (const float*)d_in[7];
    float* out = (float*)d_out;

    static void *p_xh = nullptr, *p_xl, *p_wah, *p_wal, *p_wph, *p_wpl, *p_yh, *p_yl, *p_y;
    if (!p_xh) {
        cudaGetSymbolAddress(&p_xh,  g_x_hi);  cudaGetSymbolAddress(&p_xl,  g_x_lo);
        cudaGetSymbolAddress(&p_wah, g_wa_hi); cudaGetSymbolAddress(&p_wal, g_wa_lo);
        cudaGetSymbolAddress(&p_wph, g_wp_hi); cudaGetSymbolAddress(&p_wpl, g_wp_lo);
        cudaGetSymbolAddress(&p_yh,  g_y_hi);  cudaGetSymbolAddress(&p_yl,  g_y_lo);
        cudaGetSymbolAddress(&p_y,   g_Y);
    }

    const int smem_gemm = 2 * STAGE_B;   // 81920
    const int smem_attn = 4 * 64 * PAD_ * (int)sizeof(float);
    static bool attr_set = false;
    if (!attr_set) {
        cudaFuncSetAttribute(gemm_mma_kernel, cudaFuncAttributeMaxDynamicSharedMemorySize, smem_gemm);
        cudaFuncSetAttribute(attn_kernel,     cudaFuncAttributeMaxDynamicSharedMemorySize, smem_attn);
        attr_set = true;
    }

    dim3 blk(256);

    // 1. split conversions: x, W_attn, W_proj
    split_kernel<<<(M_*C_/4 + 255)/256, blk>>>((const float4*)x,
        (uint2*)p_xh, (uint2*)p_xl, M_*C_/4);
    split_kernel<<<(3*C_*C_/4 + 255)/256, blk>>>((const float4*)W_attn,
        (uint2*)p_wah, (uint2*)p_wal, 3*C_*C_/4);
    split_kernel<<<(C_*C_/4 + 255)/256, blk>>>((const float4*)W_proj,
        (uint2*)p_wph, (uint2*)p_wpl, C_*C_/4);

    // 2. QKV GEMM (tensor cores via mma.sync) -> scatter Q/K/V with scaling
    gemm_mma_kernel<<<dim3(3*C_/128, M_/128), blk, smem_gemm>>>(
        (const __nv_bfloat16*)p_xh,  (const __nv_bfloat16*)p_xl,
        (const __nv_bfloat16*)p_wah, (const __nv_bfloat16*)p_wal,
        nullptr, 3*C_, C_, 0, w_std, w_rec, skip_std, skip_low);

    // 3. Fused causal attention + reciprocal mix
    attn_kernel<<<dim3(T_/64, B_*H_), blk, smem_attn>>>(rwr_alpha);

    // 4. split y, then output projection
    split_kernel<<<(M_*C_/4 + 255)/256, blk>>>((const float4*)p_y,
        (uint2*)p_yh, (uint2*)p_yl, M_*C_/4);
    gemm_mma_kernel<<<dim3(C_/128, M_/128), blk, smem_gemm>>>(
        (const __nv_bfloat16*)p_yh,  (const __nv_bfloat16*)p_yl,
        (const __nv_bfloat16*)p_wph, (const __nv_bfloat16*)p_wpl,
        out, C_, C_, 1, nullptr, nullptr, nullptr, nullptr);
}

// round 4
// speedup vs baseline: 3.3935x; 2.3279x over previous
#include <cuda_runtime.h>
#include <cuda_bf16.h>
#include <cstdint>
#include <math.h>

// Problem constants
#define B_    2
#define T_    2048
#define C_    1024
#define H_    16
#define D_    64
#define DSTD_ 60
#define M_    (B_*T_)   // 4096 rows

// ---------------------------------------------------------------------------
// Scratch (__device__ globals; no allocation allowed)
// ---------------------------------------------------------------------------
// bf16 hi/lo split operands for GEMMs
__device__ __nv_bfloat16 g_x_hi[M_*C_],    g_x_lo[M_*C_];
__device__ __nv_bfloat16 g_wa_hi[3*C_*C_], g_wa_lo[3*C_*C_];
__device__ __nv_bfloat16 g_wp_hi[C_*C_],   g_wp_lo[C_*C_];
__device__ __nv_bfloat16 g_y_hi[M_*C_],    g_y_lo[M_*C_];
// Q/K/V in bf16 hi/lo, [B*H, T, D]
__device__ __nv_bfloat16 g_Qh[B_*H_*T_*D_], g_Ql[B_*H_*T_*D_];
__device__ __nv_bfloat16 g_Kh[B_*H_*T_*D_], g_Kl[B_*H_*T_*D_];
__device__ __nv_bfloat16 g_Vh[B_*H_*T_*D_], g_Vl[B_*H_*T_*D_];

__device__ __forceinline__ float sigmoidf_(float v) { return 1.0f / (1.0f + __expf(-v)); }

__device__ __forceinline__ uint32_t smem_u32(const void* p) {
    return (uint32_t)__cvta_generic_to_shared(p);
}

// ---------------------------------------------------------------------------
// warp-mma helpers (baseline PTX ISA — safe for compute_103 target)
// ---------------------------------------------------------------------------
__device__ __forceinline__ void ldsm4(uint32_t* r, uint32_t addr) {
    asm volatile("ldmatrix.sync.aligned.m8n8.x4.shared.b16 {%0,%1,%2,%3}, [%4];"
        : "=r"(r[0]), "=r"(r[1]), "=r"(r[2]), "=r"(r[3]) : "r"(addr));
}

__device__ __forceinline__ void ldsm4t(uint32_t* r, uint32_t addr) {
    asm volatile("ldmatrix.sync.aligned.m8n8.x4.trans.shared.b16 {%0,%1,%2,%3}, [%4];"
        : "=r"(r[0]), "=r"(r[1]), "=r"(r[2]), "=r"(r[3]) : "r"(addr));
}

__device__ __forceinline__ void mma_bf16(float* c, const uint32_t* a, uint32_t b0, uint32_t b1) {
    asm volatile("mma.sync.aligned.m16n8k16.row.col.f32.bf16.bf16.f32 "
        "{%0,%1,%2,%3}, {%4,%5,%6,%7}, {%8,%9}, {%0,%1,%2,%3};"
        : "+f"(c[0]), "+f"(c[1]), "+f"(c[2]), "+f"(c[3])
        : "r"(a[0]), "r"(a[1]), "r"(a[2]), "r"(a[3]), "r"(b0), "r"(b1));
}

__device__ __forceinline__ void cp16(uint32_t saddr, const void* gaddr) {
    asm volatile("cp.async.cg.shared.global [%0], [%1], 16;" :: "r"(saddr), "l"(gaddr));
}

// pack two floats as bf16x2 hi, and their residuals as bf16x2 lo
__device__ __forceinline__ void split2(float x, float y, uint32_t& hi, uint32_t& lo) {
    __nv_bfloat162 h = __floats2bfloat162_rn(x, y);
    float2 hf = __bfloat1622float2(h);
    __nv_bfloat162 l = __floats2bfloat162_rn(x - hf.x, y - hf.y);
    hi = *reinterpret_cast<uint32_t*>(&h);
    lo = *reinterpret_cast<uint32_t*>(&l);
}

// ---------------------------------------------------------------------------
// fp32 -> bf16 hi/lo split (vectorized, 4 elems/thread)
// ---------------------------------------------------------------------------
__global__ __launch_bounds__(256) void split_kernel(
    const float4* __restrict__ src, uint2* __restrict__ hi, uint2* __restrict__ lo, int n4)
{
    int i = blockIdx.x * blockDim.x + threadIdx.x;
    if (i >= n4) return;
    float4 v = src[i];
    uint32_t h0, l0, h1, l1;
    split2(v.x, v.y, h0, l0);
    split2(v.z, v.w, h1, l1);
    hi[i] = make_uint2(h0, h1);
    lo[i] = make_uint2(l0, l1);
}

// ---------------------------------------------------------------------------
// Split-bf16 warp-MMA GEMM (NT): C[m,n] = sum_k A[m,k]*B[n,k], ~fp32 accuracy.
// CTA 128x128, BK=32. 8 warps as 2(m) x 4(n) -> 64x32 per warp.
// mode 0: scatter q/k/v as bf16 hi/lo with head scaling; mode 1: fp32 write.
// ---------------------------------------------------------------------------
#define OP_BYTES    10240          // 128 rows * 80 B
#define STAGE_B     (4*OP_BYTES)   // 40960

__device__ __forceinline__ void load_op(
    uint32_t sdst, const __nv_bfloat16* __restrict__ src, int Kdim, int k0, int tid)
{
#pragma unroll
    for (int p = 0; p < 2; p++) {
        int idx = tid + p * 256;        // 0..511
        int row = idx >> 2;             // 0..127
        int c8  = (idx & 3) * 8;        // bf16 col
        cp16(sdst + row * 80 + c8 * 2, src + (size_t)row * Kdim + k0 + c8);
    }
}

__global__ void __launch_bounds__(256) gemm_mma_kernel(
    const __nv_bfloat16* __restrict__ Ahi, const __nv_bfloat16* __restrict__ Alo,
    const __nv_bfloat16* __restrict__ Bhi, const __nv_bfloat16* __restrict__ Blo,
    float* __restrict__ Cout, int Ndim, int Kdim, int mode,
    const float* __restrict__ w_std, const float* __restrict__ w_rec,
    const float* __restrict__ skip_std, const float* __restrict__ skip_low)
{
    extern __shared__ char smem[];
    const uint32_t sbase = smem_u32(smem);
    const int tid  = threadIdx.x;
    const int wid  = tid >> 5;
    const int lane = tid & 31;
    const int warp_m = wid >> 2;        // 0..1
    const int warp_n = wid & 3;         // 0..3

    const int m0 = blockIdx.y * 128;
    const int n0 = blockIdx.x * 128;

    const int lr  = lane & 7, sel = lane >> 3;
    const int rowA = ((sel & 1) ? 8 : 0) + lr;
    const int kbA  = (sel & 2) ? 16 : 0;
    const int rowB = ((sel & 2) ? 8 : 0) + lr;
    const int kbB  = (sel & 1) ? 16 : 0;

    const uint32_t aoff = (uint32_t)((warp_m * 64 + rowA) * 80 + kbA);
    const uint32_t boff = (uint32_t)((warp_n * 32 + rowB) * 80 + kbB);

    const __nv_bfloat16* As_hi = Ahi + (size_t)m0 * Kdim;
    const __nv_bfloat16* As_lo = Alo + (size_t)m0 * Kdim;
    const __nv_bfloat16* Bs_hi = Bhi + (size_t)n0 * Kdim;
    const __nv_bfloat16* Bs_lo = Blo + (size_t)n0 * Kdim;

    float acc[4][4][4];
#pragma unroll
    for (int a = 0; a < 4; a++)
#pragma unroll
        for (int b = 0; b < 4; b++)
#pragma unroll
            for (int c = 0; c < 4; c++) acc[a][b][c] = 0.0f;

    const int nch = Kdim >> 5;          // BK=32

    load_op(sbase,               As_hi, Kdim, 0, tid);
    load_op(sbase +   OP_BYTES,  As_lo, Kdim, 0, tid);
    load_op(sbase + 2*OP_BYTES,  Bs_hi, Kdim, 0, tid);
    load_op(sbase + 3*OP_BYTES,  Bs_lo, Kdim, 0, tid);
    asm volatile("cp.async.commit_group;" ::: "memory");

    for (int i = 0; i < nch; i++) {
        const int s = i & 1;
        if (i + 1 < nch) {
            const uint32_t st = sbase + (uint32_t)(s ^ 1) * STAGE_B;
            const int k0 = (i + 1) << 5;
            load_op(st,               As_hi, Kdim, k0, tid);
            load_op(st +   OP_BYTES,  As_lo, Kdim, k0, tid);
            load_op(st + 2*OP_BYTES,  Bs_hi, Kdim, k0, tid);
            load_op(st + 3*OP_BYTES,  Bs_lo, Kdim, k0, tid);
            asm volatile("cp.async.commit_group;" ::: "memory");
            asm volatile("cp.async.wait_group 1;" ::: "memory");
        } else {
            asm volatile("cp.async.wait_group 0;" ::: "memory");
        }
        __syncthreads();

        const uint32_t sb = sbase + (uint32_t)s * STAGE_B;
#pragma unroll
        for (int step = 0; step < 2; step++) {
            uint32_t ah[4][4], al[4][4], bh[2][4], bl[2][4];
            const uint32_t ks = (uint32_t)(step * 32);
#pragma unroll
            for (int mt = 0; mt < 4; mt++) {
                ldsm4(ah[mt], sb + aoff + (uint32_t)(mt * 1280) + ks);
                ldsm4(al[mt], sb + OP_BYTES + aoff + (uint32_t)(mt * 1280) + ks);
            }
#pragma unroll
            for (int np = 0; np < 2; np++) {
                ldsm4(bh[np], sb + 2*OP_BYTES + boff + (uint32_t)(np * 1280) + ks);
                ldsm4(bl[np], sb + 3*OP_BYTES + boff + (uint32_t)(np * 1280) + ks);
            }
#pragma unroll
            for (int mt = 0; mt < 4; mt++)
#pragma unroll
                for (int nt = 0; nt < 4; nt++) {
                    const int np = nt >> 1, hl = (nt & 1) * 2;
                    mma_bf16(acc[mt][nt], ah[mt], bh[np][hl], bh[np][hl + 1]);
                    mma_bf16(acc[mt][nt], ah[mt], bl[np][hl], bl[np][hl + 1]);
                    mma_bf16(acc[mt][nt], al[mt], bh[np][hl], bh[np][hl + 1]);
                }
        }
        __syncthreads();
    }

    // ----------------------------- epilogue --------------------------------
    const int lr4 = lane >> 2;          // row within 8
    const int lc2 = (lane & 3) * 2;     // col pair

    if (mode == 0) {
        const int nb  = n0 + warp_n * 32;       // 32-aligned: sec & head constant
        const int sec = nb >> 10;               // 0=q 1=k 2=v
        const int f   = nb & 1023;
        const int h   = f >> 6;
        float gstd = 1.0f, grec = 1.0f;
        if (sec < 2) {
            const float ss = sigmoidf_(skip_std[0]);
            const float sl = sigmoidf_(skip_low[0]);
            // fold D^-1/4 into Q and K so scores = Q'.K'
            gstd = sqrtf(fmaxf(w_std[h] * ss, 1e-8f)) * 0.35355339059327373f;
            grec = sqrtf(fmaxf(w_rec[h] * sl, 1e-8f)) * 0.35355339059327373f;
        }
        __nv_bfloat16* dh = (sec == 0) ? g_Qh : (sec == 1) ? g_Kh : g_Vh;
        __nv_bfloat16* dl = (sec == 0) ? g_Ql : (sec == 1) ? g_Kl : g_Vl;
#pragma unroll
        for (int mt = 0; mt < 4; mt++) {
            const int r0 = m0 + warp_m * 64 + mt * 16 + lr4;
#pragma unroll
            for (int half = 0; half < 2; half++) {
                const int m = r0 + half * 8;
                const int b = m >> 11;
                const int t = m & (T_ - 1);
                const size_t base = (((size_t)(b * H_ + h)) * T_ + t) * D_;
#pragma unroll
                for (int nt = 0; nt < 4; nt++) {
                    const int d = (f & 63) + nt * 8 + lc2;
                    const float s0v = (sec < 2) ? ((d     < DSTD_) ? gstd : grec) : 1.0f;
                    const float s1v = (sec < 2) ? ((d + 1 < DSTD_) ? gstd : grec) : 1.0f;
                    uint32_t hp, lp;
                    split2(acc[mt][nt][half*2 + 0] * s0v,
                           acc[mt][nt][half*2 + 1] * s1v, hp, lp);
                    *(uint32_t*)&dh[base + d] = hp;
                    *(uint32_t*)&dl[base + d] = lp;
                }
            }
        }
    } else {
#pragma unroll
        for (int mt = 0; mt < 4; mt++) {
            const int r0 = m0 + warp_m * 64 + mt * 16 + lr4;
#pragma unroll
            for (int half = 0; half < 2; half++) {
                const int m = r0 + half * 8;
#pragma unroll
                for (int nt = 0; nt < 4; nt++) {
                    const int col = n0 + warp_n * 32 + nt * 8 + lc2;
                    float2 o;
                    o.x = acc[mt][nt][half * 2 + 0];
                    o.y = acc[mt][nt][half * 2 + 1];
                    *(float2*)&Cout[(size_t)m * Ndim + col] = o;
                }
            }
        }
    }
}

// ---------------------------------------------------------------------------
// Tensor-core causal flash attention + reciprocal mix, split-bf16.
// CTA: 256 thr (8 warps), 128 q rows (warp w owns rows w*16..w*16+15).
// K-tile = 64 kv. SMEM: double-buffered {Kh,Kl,Vh,Vl} 64x64 bf16, 144B rows.
// Epilogue writes y directly as bf16 hi/lo (feeds the proj GEMM).
// ---------------------------------------------------------------------------
#define AT_STRIDE 144
#define AT_TILE   (64*AT_STRIDE)    // 9216
#define AT_STG    (4*AT_TILE)       // 36864
#define AT_SMEM   (2*AT_STG)        // 73728

__device__ __forceinline__ void attn_load_kv(
    uint32_t sb, int k0, int tid,
    const __nv_bfloat16* Kh_g, const __nv_bfloat16* Kl_g,
    const __nv_bfloat16* Vh_g, const __nv_bfloat16* Vl_g)
{
    const __nv_bfloat16* srcs[4] = {Kh_g, Kl_g, Vh_g, Vl_g};
#pragma unroll
    for (int t4 = 0; t4 < 4; t4++) {
        const __nv_bfloat16* src = srcs[t4] + (size_t)k0 * 64;
#pragma unroll
        for (int p = 0; p < 2; p++) {
            int idx = tid + p * 256;    // 0..511
            int row = idx >> 3;         // 0..63
            int c8  = (idx & 7) * 8;
            cp16(sb + (uint32_t)(t4 * AT_TILE + row * AT_STRIDE + c8 * 2),
                 src + (size_t)row * 64 + c8);
        }
    }
}

__global__ void __launch_bounds__(256) attn_mma_kernel(const float* __restrict__ rwr_alpha)
{
    extern __shared__ char smem[];
    const uint32_t sbase = smem_u32(smem);
    const int tid  = threadIdx.x;
    const int wid  = tid >> 5;
    const int lane = tid & 31;

    const int qt = blockIdx.x;
    const int bh = blockIdx.y;
    const int q0 = qt * 128;
    const int qw = q0 + wid * 16;

    const size_t hoff = (size_t)bh * (T_ * D_);
    const __nv_bfloat16* Qh_g = g_Qh + hoff;
    const __nv_bfloat16* Ql_g = g_Ql + hoff;
    const __nv_bfloat16* Kh_g = g_Kh + hoff;
    const __nv_bfloat16* Kl_g = g_Kl + hoff;
    const __nv_bfloat16* Vh_g = g_Vh + hoff;
    const __nv_bfloat16* Vl_g = g_Vl + hoff;

    // --- load Q tile (128x64 hi+lo) into stage-0 area, extract fragments ---
#pragma unroll
    for (int p = 0; p < 4; p++) {
        int idx = tid + p * 256;        // 0..1023
        int row = idx >> 3;             // 0..127
        int c8  = (idx & 7) * 8;
        cp16(sbase + (uint32_t)(row * AT_STRIDE + c8 * 2),
             Qh_g + (size_t)(q0 + row) * 64 + c8);
        cp16(sbase + (uint32_t)(128 * AT_STRIDE + row * AT_STRIDE + c8 * 2),
             Ql_g + (size_t)(q0 + row) * 64 + c8);
    }
    asm volatile("cp.async.commit_group;" ::: "memory");
    asm volatile("cp.async.wait_group 0;" ::: "memory");
    __syncthreads();

    const int lr = lane & 7, sel = lane >> 3;
    const int rowA = ((sel & 1) ? 8 : 0) + lr;
    const int kbA  = (sel & 2) ? 16 : 0;
    const int rowB = ((sel & 2) ? 8 : 0) + lr;
    const int kbB  = (sel & 1) ? 16 : 0;

    uint32_t qh[4][4], ql[4][4];
    {
        const uint32_t qaddr = sbase + (uint32_t)((wid * 16 + rowA) * AT_STRIDE + kbA);
#pragma unroll
        for (int kc = 0; kc < 4; kc++) {
            ldsm4(qh[kc], qaddr + (uint32_t)(kc * 32));
            ldsm4(ql[kc], qaddr + (uint32_t)(128 * AT_STRIDE + kc * 32));
        }
    }
    __syncthreads();   // done reading Q region before K/V overwrite

    float O[8][4];
    float mrow[2] = {-1e30f, -1e30f}, lrow[2] = {0.0f, 0.0f};
#pragma unroll
    for (int nt = 0; nt < 8; nt++)
#pragma unroll
        for (int c = 0; c < 4; c++) O[nt][c] = 0.0f;

    const int g  = lane >> 2;           // row in 8-group
    const int t2 = (lane & 3) * 2;      // col pair

    const int nkt = 2 * qt + 2;

    attn_load_kv(sbase, 0, tid, Kh_g, Kl_g, Vh_g, Vl_g);
    asm volatile("cp.async.commit_group;" ::: "memory");

    for (int kt = 0; kt < nkt; kt++) {
        if (kt + 1 < nkt) {
            attn_load_kv(sbase + (uint32_t)((kt + 1) & 1) * AT_STG, (kt + 1) * 64, tid,
                         Kh_g, Kl_g, Vh_g, Vl_g);
            asm volatile("cp.async.commit_group;" ::: "memory");
            asm volatile("cp.async.wait_group 1;" ::: "memory");
        } else {
            asm volatile("cp.async.wait_group 0;" ::: "memory");
        }
        __syncthreads();

        const uint32_t sb = sbase + (uint32_t)(kt & 1) * AT_STG;
        const int k0 = kt * 64;

        if (k0 <= qw + 15) {            // warp has unmasked work in this tile
            // ---- S = Q.K^T (3-product split) ----
            float S[8][4];
#pragma unroll
            for (int nt = 0; nt < 8; nt++)
#pragma unroll
                for (int c = 0; c < 4; c++) S[nt][c] = 0.0f;

#pragma unroll
            for (int np = 0; np < 4; np++) {
                const uint32_t kbase = sb + (uint32_t)((np * 16 + rowB) * AT_STRIDE + kbB);
#pragma unroll
                for (int kc = 0; kc < 4; kc++) {
                    uint32_t kh[4], kl[4];
                    ldsm4(kh, kbase + (uint32_t)(kc * 32));
                    ldsm4(kl, kbase + (uint32_t)(AT_TILE + kc * 32));
                    mma_bf16(S[2*np],   qh[kc], kh[0], kh[1]);
                    mma_bf16(S[2*np],   qh[kc], kl[0], kl[1]);
                    mma_bf16(S[2*np],   ql[kc], kh[0], kh[1]);
                    mma_bf16(S[2*np+1], qh[kc], kh[2], kh[3]);
                    mma_bf16(S[2*np+1], qh[kc], kl[2], kl[3]);
                    mma_bf16(S[2*np+1], ql[kc], kh[2], kh[3]);
                }
            }

            // ---- causal mask (only the last two k-tiles can straddle) ----
            if (k0 + 63 > qw) {
#pragma unroll
                for (int nt = 0; nt < 8; nt++) {
                    const int colb = k0 + nt * 8 + t2;
#pragma unroll
                    for (int c = 0; c < 2; c++) {
                        if (colb + c > qw + g)     S[nt][c]     = -1e30f;
                        if (colb + c > qw + g + 8) S[nt][2 + c] = -1e30f;
                    }
                }
            }

            // ---- online softmax (rows g and g+8) ----
#pragma unroll
            for (int r = 0; r < 2; r++) {
                float mx = -1e30f;
#pragma unroll
                for (int nt = 0; nt < 8; nt++)
                    mx = fmaxf(mx, fmaxf(S[nt][2*r], S[nt][2*r + 1]));
                mx = fmaxf(mx, __shfl_xor_sync(0xffffffffu, mx, 1));
                mx = fmaxf(mx, __shfl_xor_sync(0xffffffffu, mx, 2));
                const float mnew = fmaxf(mrow[r], mx);
                const float corr = __expf(mrow[r] - mnew);
                float ls = 0.0f;
#pragma unroll
                for (int nt = 0; nt < 8; nt++) {
                    S[nt][2*r]     = __expf(S[nt][2*r]     - mnew);
                    S[nt][2*r + 1] = __expf(S[nt][2*r + 1] - mnew);
                    ls += S[nt][2*r] + S[nt][2*r + 1];
                }
                ls += __shfl_xor_sync(0xffffffffu, ls, 1);
                ls += __shfl_xor_sync(0xffffffffu, ls, 2);
                lrow[r] = lrow[r] * corr + ls;
                mrow[r] = mnew;
#pragma unroll
                for (int nt = 0; nt < 8; nt++) {
                    O[nt][2*r]     *= corr;
                    O[nt][2*r + 1] *= corr;
                }
            }

            // ---- O += P.V (P from S frags in-register; 3-product split) ----
#pragma unroll
            for (int kc = 0; kc < 4; kc++) {
                uint32_t pah[4], pal[4];
                split2(S[2*kc][0],   S[2*kc][1],   pah[0], pal[0]);
                split2(S[2*kc][2],   S[2*kc][3],   pah[1], pal[1]);
                split2(S[2*kc+1][0], S[2*kc+1][1], pah[2], pal[2]);
                split2(S[2*kc+1][2], S[2*kc+1][3], pah[3], pal[3]);
#pragma unroll
                for (int nd = 0; nd < 4; nd++) {
                    uint32_t vh[4], vl[4];
                    const uint32_t vaddr = sb + (uint32_t)(2 * AT_TILE
                        + (kc * 16 + (lane & 15)) * AT_STRIDE
                        + nd * 32 + ((lane & 16) ? 16 : 0));
                    ldsm4t(vh, vaddr);
                    ldsm4t(vl, vaddr + AT_TILE);
                    mma_bf16(O[2*nd],   pah, vh[0], vh[1]);
                    mma_bf16(O[2*nd],   pah, vl[0], vl[1]);
                    mma_bf16(O[2*nd],   pal, vh[0], vh[1]);
                    mma_bf16(O[2*nd+1], pah, vh[2], vh[3]);
                    mma_bf16(O[2*nd+1], pah, vl[2], vl[3]);
                    mma_bf16(O[2*nd+1], pal, vh[2], vh[3]);
                }
            }
        }
        __syncthreads();   // all warps done with this stage before re-fill
    }

    // ---- epilogue: normalize, reciprocal mix, write y as bf16 hi/lo ----
    const int h = bh & (H_ - 1);
    const int b = bh >> 4;
    const float alpha = fminf(fmaxf(rwr_alpha[h], 0.0f), 0.5f);
    const float om = 1.0f - alpha;

#pragma unroll
    for (int r = 0; r < 2; r++) {
        const int q = qw + g + r * 8;
        const float inv = 1.0f / lrow[r];
        const size_t vrow = (size_t)q * 64;
        const size_t orow = ((size_t)(b * T_ + q)) * C_ + h * 64;
#pragma unroll
        for (int nt = 0; nt < 8; nt++) {
            const int d = nt * 8 + t2;
            const uint32_t uvh = *(const uint32_t*)&Vh_g[vrow + d];
            const uint32_t uvl = *(const uint32_t*)&Vl_g[vrow + d];
            const float2 fh = __bfloat1622float2(*(const __nv_bfloat162*)&uvh);
            const float2 fl = __bfloat1622float2(*(const __nv_bfloat162*)&uvl);
            const float y0 = om * (O[nt][2*r]     * inv) + alpha * (fh.x + fl.x);
            const float y1 = om * (O[nt][2*r + 1] * inv) + alpha * (fh.y + fl.y);
            uint32_t hp, lp;
            split2(y0, y1, hp, lp);
            *(uint32_t*)&g_y_hi[orow + d] = hp;
            *(uint32_t*)&g_y_lo[orow + d] = lp;
        }
    }
}

// ---------------------------------------------------------------------------
extern "C" void kernel_launch(void* const* d_in, const int* in_sizes, int n_in,
                              void* d_out, int out_size)
{
    const float* x         = (const float*)d_in[0];
    const float* W_attn    = (const float*)d_in[1];
    const float* W_proj    = (const float*)d_in[2];
    const float* w_std     = (const float*)d_in[3];
    const float* w_rec     = (const float*)d_in[4];
    const float* skip_std  = (const float*)d_in[5];
    const float* skip_low  = (const float*)d_in[6];
    const float* rwr_alpha = (const float*)d_in[7];
    float* out = (float*)d_out;

    static void *p_xh = nullptr, *p_xl, *p_wah, *p_wal, *p_wph, *p_wpl, *p_yh, *p_yl;
    if (!p_xh) {
        cudaGetSymbolAddress(&p_xh,  g_x_hi);  cudaGetSymbolAddress(&p_xl,  g_x_lo);
        cudaGetSymbolAddress(&p_wah, g_wa_hi); cudaGetSymbolAddress(&p_wal, g_wa_lo);
        cudaGetSymbolAddress(&p_wph, g_wp_hi); cudaGetSymbolAddress(&p_wpl, g_wp_lo);
        cudaGetSymbolAddress(&p_yh,  g_y_hi);  cudaGetSymbolAddress(&p_yl,  g_y_lo);
    }

    const int smem_gemm = 2 * STAGE_B;   // 81920
    static bool attr_set = false;
    if (!attr_set) {
        cudaFuncSetAttribute(gemm_mma_kernel, cudaFuncAttributeMaxDynamicSharedMemorySize, smem_gemm);
        cudaFuncSetAttribute(attn_mma_kernel, cudaFuncAttributeMaxDynamicSharedMemorySize, AT_SMEM);
        attr_set = true;
    }

    dim3 blk(256);

    // 1. split conversions: x, W_attn, W_proj
    split_kernel<<<(M_*C_/4 + 255)/256, blk>>>((const float4*)x,
        (uint2*)p_xh, (uint2*)p_xl, M_*C_/4);
    split_kernel<<<(3*C_*C_/4 + 255)/256, blk>>>((const float4*)W_attn,
        (uint2*)p_wah, (uint2*)p_wal, 3*C_*C_/4);
    split_kernel<<<(C_*C_/4 + 255)/256, blk>>>((const float4*)W_proj,
        (uint2*)p_wph, (uint2*)p_wpl, C_*C_/4);

    // 2. QKV GEMM -> Q/K/V bf16 hi/lo with head scaling folded in
    gemm_mma_kernel<<<dim3(3*C_/128, M_/128), blk, smem_gemm>>>(
        (const __nv_bfloat16*)p_xh,  (const __nv_bfloat16*)p_xl,
        (const __nv_bfloat16*)p_wah, (const __nv_bfloat16*)p_wal,
        nullptr, 3*C_, C_, 0, w_std, w_rec, skip_std, skip_low);

    // 3. Tensor-core causal attention + reciprocal mix -> y bf16 hi/lo
    attn_mma_kernel<<<dim3(T_/128, B_*H_), blk, AT_SMEM>>>(rwr_alpha);

    // 4. output projection
    gemm_mma_kernel<<<dim3(C_/128, M_/128), blk, smem_gemm>>>(
        (const __nv_bfloat16*)p_yh,  (const __nv_bfloat16*)p_yl,
        (const __nv_bfloat16*)p_wph, (const __nv_bfloat16*)p_wpl,
        out, C_, C_, 1, nullptr, nullptr, nullptr, nullptr);
}

// round 5
// speedup vs baseline: 8.5627x; 2.5233x over previous
#include <cuda_runtime.h>
#include <cuda_fp16.h>
#include <cstdint>
#include <math.h>

// Problem constants
#define B_    2
#define T_    2048
#define C_    1024
#define H_    16
#define D_    64
#define DSTD_ 60
#define M_    (B_*T_)   // 4096 rows

// ---------------------------------------------------------------------------
// Scratch (__device__ globals; no allocation allowed)
// ---------------------------------------------------------------------------
__device__ __half g_x16[M_*C_];
__device__ __half g_wa16[3*C_*C_];
__device__ __half g_wp16[C_*C_];
__device__ __half g_y16[M_*C_];
__device__ __half g_q16[B_*H_*T_*D_];   // [B*H, T, D]
__device__ __half g_k16[B_*H_*T_*D_];
__device__ __half g_v16[B_*H_*T_*D_];

__device__ __forceinline__ float sigmoidf_(float v) { return 1.0f / (1.0f + __expf(-v)); }

__device__ __forceinline__ uint32_t smem_u32(const void* p) {
    return (uint32_t)__cvta_generic_to_shared(p);
}

__device__ __forceinline__ float ex2_(float x) {
    float r; asm("ex2.approx.f32 %0, %1;" : "=f"(r) : "f"(x)); return r;
}

// ---------------------------------------------------------------------------
// warp-mma helpers (baseline PTX ISA — safe for compute_103 target)
// ---------------------------------------------------------------------------
__device__ __forceinline__ void ldsm4(uint32_t* r, uint32_t addr) {
    asm volatile("ldmatrix.sync.aligned.m8n8.x4.shared.b16 {%0,%1,%2,%3}, [%4];"
        : "=r"(r[0]), "=r"(r[1]), "=r"(r[2]), "=r"(r[3]) : "r"(addr));
}

__device__ __forceinline__ void ldsm4t(uint32_t* r, uint32_t addr) {
    asm volatile("ldmatrix.sync.aligned.m8n8.x4.trans.shared.b16 {%0,%1,%2,%3}, [%4];"
        : "=r"(r[0]), "=r"(r[1]), "=r"(r[2]), "=r"(r[3]) : "r"(addr));
}

__device__ __forceinline__ void mma_f16(float* c, const uint32_t* a, uint32_t b0, uint32_t b1) {
    asm volatile("mma.sync.aligned.m16n8k16.row.col.f32.f16.f16.f32 "
        "{%0,%1,%2,%3}, {%4,%5,%6,%7}, {%8,%9}, {%0,%1,%2,%3};"
        : "+f"(c[0]), "+f"(c[1]), "+f"(c[2]), "+f"(c[3])
        : "r"(a[0]), "r"(a[1]), "r"(a[2]), "r"(a[3]), "r"(b0), "r"(b1));
}

__device__ __forceinline__ void cp16(uint32_t saddr, const void* gaddr) {
    asm volatile("cp.async.cg.shared.global [%0], [%1], 16;" :: "r"(saddr), "l"(gaddr));
}

// ---------------------------------------------------------------------------
// fused fp32 -> fp16 convert for x, W_attn, W_proj (one launch)
// ---------------------------------------------------------------------------
#define NX4_  (M_*C_/4)       // 1048576
#define NWA4_ (3*C_*C_/4)     // 786432
#define NWP4_ (C_*C_/4)       // 262144
#define NTOT4_ (NX4_+NWA4_+NWP4_)

__global__ __launch_bounds__(256) void conv_kernel(
    const float4* __restrict__ x, const float4* __restrict__ wa, const float4* __restrict__ wp)
{
    int i = blockIdx.x * blockDim.x + threadIdx.x;
    if (i >= NTOT4_) return;
    const float4* s; uint2* d; int o;
    if (i < NX4_)              { s = x;  d = (uint2*)g_x16;  o = i; }
    else if (i < NX4_ + NWA4_) { s = wa; d = (uint2*)g_wa16; o = i - NX4_; }
    else                       { s = wp; d = (uint2*)g_wp16; o = i - NX4_ - NWA4_; }
    float4 v = s[o];
    __half2 a = __floats2half2_rn(v.x, v.y);
    __half2 b = __floats2half2_rn(v.z, v.w);
    d[o] = make_uint2(*(uint32_t*)&a, *(uint32_t*)&b);
}

// ---------------------------------------------------------------------------
// fp16 warp-MMA GEMM (NT): C[m,n] = sum_k A[m,k]*B[n,k].
// CTA 128x128, BK=64, 3-stage cp.async ring, ONE barrier per chunk.
// 8 warps as 2(m) x 4(n) -> 64x32 per warp. 144B-padded rows.
// mode 0: scatter q/k/v fp16 with head scaling (sqrt(log2 e) folded for q,k);
// mode 1: plain fp32 write.
// ---------------------------------------------------------------------------
#define GS_OP   18432          // 128 rows * 144 B
#define GS_STG  (2*GS_OP)      // 36864 (A + B)
#define GS_SMEM (3*GS_STG)     // 110592

// scale const: D^-1/4 * sqrt(log2(e)) = 0.35355339 * 1.20112241
#define QK_SCALE 0.42466089786070306f

__device__ __forceinline__ void load_op64(
    uint32_t sdst, const __half* __restrict__ src, int Kdim, int k0, int tid)
{
#pragma unroll
    for (int p = 0; p < 4; p++) {
        int idx = tid + p * 256;        // 0..1023
        int row = idx >> 3;             // 0..127
        int c8  = (idx & 7) * 8;        // half col
        cp16(sdst + (uint32_t)(row * 144 + c8 * 2), src + (size_t)row * Kdim + k0 + c8);
    }
}

__global__ void __launch_bounds__(256, 2) gemm_f16_kernel(
    const __half* __restrict__ A, const __half* __restrict__ Bm,
    float* __restrict__ Cout, int Ndim, int Kdim, int mode,
    const float* __restrict__ w_std, const float* __restrict__ w_rec,
    const float* __restrict__ skip_std, const float* __restrict__ skip_low)
{
    extern __shared__ char smem[];
    const uint32_t sbase = smem_u32(smem);
    const int tid  = threadIdx.x;
    const int wid  = tid >> 5;
    const int lane = tid & 31;
    const int warp_m = wid >> 2;        // 0..1
    const int warp_n = wid & 3;         // 0..3

    const int m0 = blockIdx.y * 128;
    const int n0 = blockIdx.x * 128;

    const int lr = lane & 7, sel = lane >> 3;
    const int rowA = ((sel & 1) ? 8 : 0) + lr;
    const int kbA  = (sel & 2) ? 16 : 0;
    const int rowB = ((sel & 2) ? 8 : 0) + lr;
    const int kbB  = (sel & 1) ? 16 : 0;

    const uint32_t aoff = (uint32_t)((warp_m * 64 + rowA) * 144 + kbA);
    const uint32_t boff = (uint32_t)(GS_OP + (warp_n * 32 + rowB) * 144 + kbB);

    const __half* Ag = A  + (size_t)m0 * Kdim;
    const __half* Bg = Bm + (size_t)n0 * Kdim;

    float acc[4][4][4];
#pragma unroll
    for (int a = 0; a < 4; a++)
#pragma unroll
        for (int b = 0; b < 4; b++)
#pragma unroll
            for (int c = 0; c < 4; c++) acc[a][b][c] = 0.0f;

    const int nch = Kdim >> 6;          // BK=64

    // prologue: chunks 0,1 into stages 0,1
    load_op64(sbase,          Ag, Kdim, 0, tid);
    load_op64(sbase + GS_OP,  Bg, Kdim, 0, tid);
    asm volatile("cp.async.commit_group;" ::: "memory");
    load_op64(sbase + GS_STG,         Ag, Kdim, 64, tid);
    load_op64(sbase + GS_STG + GS_OP, Bg, Kdim, 64, tid);
    asm volatile("cp.async.commit_group;" ::: "memory");

    for (int i = 0; i < nch; i++) {
        if (i + 1 < nch) asm volatile("cp.async.wait_group 1;" ::: "memory");
        else             asm volatile("cp.async.wait_group 0;" ::: "memory");
        __syncthreads();
        // loads for chunk i+2 issued AFTER the barrier: the stage being
        // overwritten was last read in chunk i-1, and every warp passed this
        // barrier only after finishing chunk i-1's MMAs -> race-free, 1 bar.
        if (i + 2 < nch) {
            const uint32_t st = sbase + (uint32_t)((i + 2) % 3) * GS_STG;
            load_op64(st,         Ag, Kdim, (i + 2) << 6, tid);
            load_op64(st + GS_OP, Bg, Kdim, (i + 2) << 6, tid);
            asm volatile("cp.async.commit_group;" ::: "memory");
        }
        const uint32_t sb = sbase + (uint32_t)(i % 3) * GS_STG;
#pragma unroll
        for (int ks = 0; ks < 4; ks++) {
            uint32_t a4[4][4], b4[2][4];
#pragma unroll
            for (int mt = 0; mt < 4; mt++)
                ldsm4(a4[mt], sb + aoff + (uint32_t)(mt * 2304 + ks * 32));
#pragma unroll
            for (int np = 0; np < 2; np++)
                ldsm4(b4[np], sb + boff + (uint32_t)(np * 2304 + ks * 32));
#pragma unroll
            for (int mt = 0; mt < 4; mt++)
#pragma unroll
                for (int nt = 0; nt < 4; nt++)
                    mma_f16(acc[mt][nt], a4[mt],
                            b4[nt >> 1][(nt & 1) * 2], b4[nt >> 1][(nt & 1) * 2 + 1]);
        }
    }

    // ----------------------------- epilogue --------------------------------
    const int lr4 = lane >> 2;
    const int lc2 = (lane & 3) * 2;

    if (mode == 0) {
        const int nb  = n0 + warp_n * 32;       // 32-aligned: sec & head constant
        const int sec = nb >> 10;               // 0=q 1=k 2=v
        const int f   = nb & 1023;
        const int h   = f >> 6;
        float gstd = 1.0f, grec = 1.0f;
        if (sec < 2) {
            const float ss = sigmoidf_(skip_std[0]);
            const float sl = sigmoidf_(skip_low[0]);
            gstd = sqrtf(fmaxf(w_std[h] * ss, 1e-8f)) * QK_SCALE;
            grec = sqrtf(fmaxf(w_rec[h] * sl, 1e-8f)) * QK_SCALE;
        }
        __half* dst = (sec == 0) ? g_q16 : (sec == 1) ? g_k16 : g_v16;
#pragma unroll
        for (int mt = 0; mt < 4; mt++) {
            const int r0 = m0 + warp_m * 64 + mt * 16 + lr4;
#pragma unroll
            for (int half = 0; half < 2; half++) {
                const int m = r0 + half * 8;
                const int b = m >> 11;
                const int t = m & (T_ - 1);
                const size_t base = (((size_t)(b * H_ + h)) * T_ + t) * D_;
#pragma unroll
                for (int nt = 0; nt < 4; nt++) {
                    const int d = (f & 63) + nt * 8 + lc2;
                    const float s0 = (sec < 2) ? ((d     < DSTD_) ? gstd : grec) : 1.0f;
                    const float s1 = (sec < 2) ? ((d + 1 < DSTD_) ? gstd : grec) : 1.0f;
                    __half2 hv = __floats2half2_rn(acc[mt][nt][half*2 + 0] * s0,
                                                   acc[mt][nt][half*2 + 1] * s1);
                    *(uint32_t*)&dst[base + d] = *(uint32_t*)&hv;
                }
            }
        }
    } else {
#pragma unroll
        for (int mt = 0; mt < 4; mt++) {
            const int r0 = m0 + warp_m * 64 + mt * 16 + lr4;
#pragma unroll
            for (int half = 0; half < 2; half++) {
                const int m = r0 + half * 8;
#pragma unroll
                for (int nt = 0; nt < 4; nt++) {
                    const int col = n0 + warp_n * 32 + nt * 8 + lc2;
                    float2 o;
                    o.x = acc[mt][nt][half * 2 + 0];
                    o.y = acc[mt][nt][half * 2 + 1];
                    *(float2*)&Cout[(size_t)m * Ndim + col] = o;
                }
            }
        }
    }
}

// ---------------------------------------------------------------------------
// fp16 tensor-core causal flash attention + reciprocal mix.
// CTA: 8 warps, 128 q rows (warp w owns rows w*16..+15). KV tile = 64.
// SMEM: Q (128x64, 144B rows) + 3-stage {K,V} ring, ONE barrier per tile.
// Softmax in exp2 domain (log2 e folded into Q/K scales by the GEMM).
// Epilogue writes y fp16 (feeds the proj GEMM).
// ---------------------------------------------------------------------------
#define AQ_B    18432               // Q region: 128*144
#define AT_T    9216                // one 64x144 tile
#define AT_STG2 (2*AT_T)            // K+V stage
#define AT_SMEM (AQ_B + 3*AT_STG2)  // 73728

__device__ __forceinline__ void attn_load_kv16(
    uint32_t sb, int k0, int tid,
    const __half* __restrict__ Kg, const __half* __restrict__ Vg)
{
#pragma unroll
    for (int p = 0; p < 2; p++) {
        int idx = tid + p * 256;    // 0..511
        int row = idx >> 3;         // 0..63
        int c8  = (idx & 7) * 8;
        cp16(sb + (uint32_t)(row * 144 + c8 * 2),        Kg + (size_t)(k0 + row) * 64 + c8);
        cp16(sb + (uint32_t)(AT_T + row * 144 + c8 * 2), Vg + (size_t)(k0 + row) * 64 + c8);
    }
}

__global__ void __launch_bounds__(256, 2) attn_f16_kernel(const float* __restrict__ rwr_alpha)
{
    extern __shared__ char smem[];
    const uint32_t sbase = smem_u32(smem);
    const int tid  = threadIdx.x;
    const int wid  = tid >> 5;
    const int lane = tid & 31;

    const int qt = blockIdx.x;
    const int bh = blockIdx.y;
    const int q0 = qt * 128;
    const int qw = q0 + wid * 16;

    const size_t hoff = (size_t)bh * (T_ * D_);
    const __half* Qg = g_q16 + hoff;
    const __half* Kg = g_k16 + hoff;
    const __half* Vg = g_v16 + hoff;

    // Q tile load (group 0)
#pragma unroll
    for (int p = 0; p < 4; p++) {
        int idx = tid + p * 256;
        int row = idx >> 3;
        int c8  = (idx & 7) * 8;
        cp16(sbase + (uint32_t)(row * 144 + c8 * 2), Qg + (size_t)(q0 + row) * 64 + c8);
    }
    asm volatile("cp.async.commit_group;" ::: "memory");

    const int nkt = 2 * qt + 2;

    // prologue KV tiles 0,1 (groups 1,2)
    attn_load_kv16(sbase + AQ_B,           0,  tid, Kg, Vg);
    asm volatile("cp.async.commit_group;" ::: "memory");
    attn_load_kv16(sbase + AQ_B + AT_STG2, 64, tid, Kg, Vg);
    asm volatile("cp.async.commit_group;" ::: "memory");

    // wait for Q, extract fragments (Q region never overwritten)
    asm volatile("cp.async.wait_group 2;" ::: "memory");
    __syncthreads();

    const int lr = lane & 7, sel = lane >> 3;
    const int rowA = ((sel & 1) ? 8 : 0) + lr;
    const int kbA  = (sel & 2) ? 16 : 0;
    const int rowB = ((sel & 2) ? 8 : 0) + lr;
    const int kbB  = (sel & 1) ? 16 : 0;

    uint32_t qh[4][4];
    {
        const uint32_t qaddr = sbase + (uint32_t)((wid * 16 + rowA) * 144 + kbA);
#pragma unroll
        for (int kc = 0; kc < 4; kc++) ldsm4(qh[kc], qaddr + (uint32_t)(kc * 32));
    }

    float O[8][4];
    float mrow[2] = {-1e30f, -1e30f}, lrow[2] = {0.0f, 0.0f};
#pragma unroll
    for (int nt = 0; nt < 8; nt++)
#pragma unroll
        for (int c = 0; c < 4; c++) O[nt][c] = 0.0f;

    const int g  = lane >> 2;
    const int t2 = (lane & 3) * 2;

    for (int kt = 0; kt < nkt; kt++) {
        if (kt + 1 < nkt) asm volatile("cp.async.wait_group 1;" ::: "memory");
        else              asm volatile("cp.async.wait_group 0;" ::: "memory");
        __syncthreads();
        if (kt + 2 < nkt) {
            attn_load_kv16(sbase + AQ_B + (uint32_t)((kt + 2) % 3) * AT_STG2,
                           (kt + 2) * 64, tid, Kg, Vg);
            asm volatile("cp.async.commit_group;" ::: "memory");
        }

        const uint32_t sb = sbase + AQ_B + (uint32_t)(kt % 3) * AT_STG2;
        const int k0 = kt * 64;

        if (k0 <= qw + 15) {
            // ---- S = Q.K^T (single fp16 product; scores in log2 domain) ----
            float S[8][4];
#pragma unroll
            for (int nt = 0; nt < 8; nt++)
#pragma unroll
                for (int c = 0; c < 4; c++) S[nt][c] = 0.0f;

#pragma unroll
            for (int np = 0; np < 4; np++) {
                const uint32_t kb_ = sb + (uint32_t)((np * 16 + rowB) * 144 + kbB);
#pragma unroll
                for (int kc = 0; kc < 4; kc++) {
                    uint32_t k4[4];
                    ldsm4(k4, kb_ + (uint32_t)(kc * 32));
                    mma_f16(S[2*np],     qh[kc], k4[0], k4[1]);
                    mma_f16(S[2*np + 1], qh[kc], k4[2], k4[3]);
                }
            }

            // ---- causal mask ----
            if (k0 + 63 > qw) {
#pragma unroll
                for (int nt = 0; nt < 8; nt++) {
                    const int colb = k0 + nt * 8 + t2;
#pragma unroll
                    for (int c = 0; c < 2; c++) {
                        if (colb + c > qw + g)     S[nt][c]     = -1e30f;
                        if (colb + c > qw + g + 8) S[nt][2 + c] = -1e30f;
                    }
                }
            }

            // ---- online softmax (exp2 domain) ----
#pragma unroll
            for (int r = 0; r < 2; r++) {
                float mx = -1e30f;
#pragma unroll
                for (int nt = 0; nt < 8; nt++)
                    mx = fmaxf(mx, fmaxf(S[nt][2*r], S[nt][2*r + 1]));
                mx = fmaxf(mx, __shfl_xor_sync(0xffffffffu, mx, 1));
                mx = fmaxf(mx, __shfl_xor_sync(0xffffffffu, mx, 2));
                const float mnew = fmaxf(mrow[r], mx);
                const float corr = ex2_(mrow[r] - mnew);
                float ls = 0.0f;
#pragma unroll
                for (int nt = 0; nt < 8; nt++) {
                    S[nt][2*r]     = ex2_(S[nt][2*r]     - mnew);
                    S[nt][2*r + 1] = ex2_(S[nt][2*r + 1] - mnew);
                    ls += S[nt][2*r] + S[nt][2*r + 1];
                }
                ls += __shfl_xor_sync(0xffffffffu, ls, 1);
                ls += __shfl_xor_sync(0xffffffffu, ls, 2);
                lrow[r] = lrow[r] * corr + ls;
                mrow[r] = mnew;
#pragma unroll
                for (int nt = 0; nt < 8; nt++) {
                    O[nt][2*r]     *= corr;
                    O[nt][2*r + 1] *= corr;
                }
            }

            // ---- O += P.V (P packed fp16 in-register) ----
#pragma unroll
            for (int kc = 0; kc < 4; kc++) {
                uint32_t pa[4];
                {
                    __half2 p0 = __floats2half2_rn(S[2*kc][0],   S[2*kc][1]);
                    __half2 p1 = __floats2half2_rn(S[2*kc][2],   S[2*kc][3]);
                    __half2 p2 = __floats2half2_rn(S[2*kc+1][0], S[2*kc+1][1]);
                    __half2 p3 = __floats2half2_rn(S[2*kc+1][2], S[2*kc+1][3]);
                    pa[0] = *(uint32_t*)&p0; pa[1] = *(uint32_t*)&p1;
                    pa[2] = *(uint32_t*)&p2; pa[3] = *(uint32_t*)&p3;
                }
#pragma unroll
                for (int nd = 0; nd < 4; nd++) {
                    uint32_t v4[4];
                    const uint32_t vaddr = sb + (uint32_t)(AT_T
                        + (kc * 16 + (lane & 15)) * 144
                        + nd * 32 + ((lane & 16) ? 16 : 0));
                    ldsm4t(v4, vaddr);
                    mma_f16(O[2*nd],     pa, v4[0], v4[1]);
                    mma_f16(O[2*nd + 1], pa, v4[2], v4[3]);
                }
            }
        }
    }

    // ---- epilogue: normalize, reciprocal mix, write y fp16 ----
    const int h = bh & (H_ - 1);
    const int b = bh >> 4;
    const float alpha = fminf(fmaxf(rwr_alpha[h], 0.0f), 0.5f);
    const float om = 1.0f - alpha;

#pragma unroll
    for (int r = 0; r < 2; r++) {
        const int q = qw + g + r * 8;
        const float inv = 1.0f / lrow[r];
        const size_t vrow = (size_t)q * 64;
        const size_t orow = ((size_t)(b * T_ + q)) * C_ + h * 64;
#pragma unroll
        for (int nt = 0; nt < 8; nt++) {
            const int d = nt * 8 + t2;
            const uint32_t uv = *(const uint32_t*)&Vg[vrow + d];
            const float2 fv = __half22float2(*(const __half2*)&uv);
            const float y0 = om * (O[nt][2*r]     * inv) + alpha * fv.x;
            const float y1 = om * (O[nt][2*r + 1] * inv) + alpha * fv.y;
            __half2 hy = __floats2half2_rn(y0, y1);
            *(uint32_t*)&g_y16[orow + d] = *(uint32_t*)&hy;
        }
    }
}

// ---------------------------------------------------------------------------
extern "C" void kernel_launch(void* const* d_in, const int* in_sizes, int n_in,
                              void* d_out, int out_size)
{
    const float* x         = (const float*)d_in[0];
    const float* W_attn    = (const float*)d_in[1];
    const float* W_proj    = (const float*)d_in[2];
    const float* w_std     = (const float*)d_in[3];
    const float* w_rec     = (const float*)d_in[4];
    const float* skip_std  = (const float*)d_in[5];
    const float* skip_low  = (const float*)d_in[6];
    const float* rwr_alpha = (const float*)d_in[7];
    float* out = (float*)d_out;

    static void *p_x16 = nullptr, *p_wa16, *p_wp16, *p_y16;
    if (!p_x16) {
        cudaGetSymbolAddress(&p_x16,  g_x16);
        cudaGetSymbolAddress(&p_wa16, g_wa16);
        cudaGetSymbolAddress(&p_wp16, g_wp16);
        cudaGetSymbolAddress(&p_y16,  g_y16);
    }

    static bool attr_set = false;
    if (!attr_set) {
        cudaFuncSetAttribute(gemm_f16_kernel, cudaFuncAttributeMaxDynamicSharedMemorySize, GS_SMEM);
        cudaFuncSetAttribute(attn_f16_kernel, cudaFuncAttributeMaxDynamicSharedMemorySize, AT_SMEM);
        attr_set = true;
    }

    dim3 blk(256);

    // 1. fused fp32 -> fp16 conversion (x, W_attn, W_proj)
    conv_kernel<<<(NTOT4_ + 255) / 256, blk>>>(
        (const float4*)x, (const float4*)W_attn, (const float4*)W_proj);

    // 2. QKV GEMM -> q/k/v fp16 with head scaling (+ log2e fold for q,k)
    gemm_f16_kernel<<<dim3(3*C_/128, M_/128), blk, GS_SMEM>>>(
        (const __half*)p_x16, (const __half*)p_wa16,
        nullptr, 3*C_, C_, 0, w_std, w_rec, skip_std, skip_low);

    // 3. fp16 tensor-core causal attention + reciprocal mix -> y fp16
    attn_f16_kernel<<<dim3(T_/128, B_*H_), blk, AT_SMEM>>>(rwr_alpha);

    // 4. output projection -> fp32 out
    gemm_f16_kernel<<<dim3(C_/128, M_/128), blk, GS_SMEM>>>(
        (const __half*)p_y16, (const __half*)p_wp16,
        out, C_, C_, 1, nullptr, nullptr, nullptr, nullptr);
}

// round 8
// speedup vs baseline: 8.7064x; 1.0168x over previous
#include <cuda_runtime.h>
#include <cuda_fp16.h>
#include <cstdint>
#include <math.h>

// Problem constants
#define B_    2
#define T_    2048
#define C_    1024
#define H_    16
#define D_    64
#define DSTD_ 60
#define M_    (B_*T_)   // 4096 rows

// ---------------------------------------------------------------------------
// Scratch (__device__ globals; no allocation allowed)
// ---------------------------------------------------------------------------
__device__ __half g_x16[M_*C_];
__device__ __half g_wa16[3*C_*C_];
__device__ __half g_wp16[C_*C_];
__device__ __half g_y16[M_*C_];
__device__ __half g_q16[B_*H_*T_*D_];   // [B*H, T, D]
__device__ __half g_k16[B_*H_*T_*D_];
__device__ __half g_v16[B_*H_*T_*D_];

__device__ __forceinline__ float sigmoidf_(float v) { return 1.0f / (1.0f + __expf(-v)); }

__device__ __forceinline__ uint32_t smem_u32(const void* p) {
    return (uint32_t)__cvta_generic_to_shared(p);
}

__device__ __forceinline__ float ex2_(float x) {
    float r; asm("ex2.approx.f32 %0, %1;" : "=f"(r) : "f"(x)); return r;
}
__device__ __forceinline__ uint32_t ex2h2_(uint32_t x) {
    uint32_t r; asm("ex2.approx.f16x2 %0, %1;" : "=r"(r) : "r"(x)); return r;
}
__device__ __forceinline__ uint32_t packh2_(float x, float y) {
    __half2 h = __floats2half2_rn(x, y);
    return *reinterpret_cast<uint32_t*>(&h);
}

// ---------------------------------------------------------------------------
// warp-mma helpers (baseline PTX ISA — safe for compute_103 target)
// ---------------------------------------------------------------------------
__device__ __forceinline__ void ldsm4(uint32_t* r, uint32_t addr) {
    asm volatile("ldmatrix.sync.aligned.m8n8.x4.shared.b16 {%0,%1,%2,%3}, [%4];"
        : "=r"(r[0]), "=r"(r[1]), "=r"(r[2]), "=r"(r[3]) : "r"(addr));
}

__device__ __forceinline__ void ldsm4t(uint32_t* r, uint32_t addr) {
    asm volatile("ldmatrix.sync.aligned.m8n8.x4.trans.shared.b16 {%0,%1,%2,%3}, [%4];"
        : "=r"(r[0]), "=r"(r[1]), "=r"(r[2]), "=r"(r[3]) : "r"(addr));
}

__device__ __forceinline__ void mma_f16(float* c, const uint32_t* a, uint32_t b0, uint32_t b1) {
    asm volatile("mma.sync.aligned.m16n8k16.row.col.f32.f16.f16.f32 "
        "{%0,%1,%2,%3}, {%4,%5,%6,%7}, {%8,%9}, {%0,%1,%2,%3};"
        : "+f"(c[0]), "+f"(c[1]), "+f"(c[2]), "+f"(c[3])
        : "r"(a[0]), "r"(a[1]), "r"(a[2]), "r"(a[3]), "r"(b0), "r"(b1));
}

__device__ __forceinline__ void cp16(uint32_t saddr, const void* gaddr) {
    asm volatile("cp.async.cg.shared.global [%0], [%1], 16;" :: "r"(saddr), "l"(gaddr));
}

// ---------------------------------------------------------------------------
// fused fp32 -> fp16 convert for x, W_attn, W_proj (one launch)
// ---------------------------------------------------------------------------
#define NX4_  (M_*C_/4)       // 1048576
#define NWA4_ (3*C_*C_/4)     // 786432
#define NWP4_ (C_*C_/4)       // 262144
#define NTOT4_ (NX4_+NWA4_+NWP4_)

__global__ __launch_bounds__(256) void conv_kernel(
    const float4* __restrict__ x, const float4* __restrict__ wa, const float4* __restrict__ wp)
{
    int i = blockIdx.x * blockDim.x + threadIdx.x;
    if (i >= NTOT4_) return;
    const float4* s; uint2* d; int o;
    if (i < NX4_)              { s = x;  d = (uint2*)g_x16;  o = i; }
    else if (i < NX4_ + NWA4_) { s = wa; d = (uint2*)g_wa16; o = i - NX4_; }
    else                       { s = wp; d = (uint2*)g_wp16; o = i - NX4_ - NWA4_; }
    float4 v = s[o];
    d[o] = make_uint2(packh2_(v.x, v.y), packh2_(v.z, v.w));
}

// ---------------------------------------------------------------------------
// fp16 warp-MMA GEMM (NT): C[m,n] = sum_k A[m,k]*B[n,k].
// CTA 128x128, 128 threads, 4 warps as 2(m) x 2(n) -> 64x64 per warp.
// BK=64, 3-stage cp.async ring, ONE barrier per chunk. 144B-padded rows.
// mode 0: scatter q/k/v fp16 with head scaling (sqrt(log2 e) folded for q,k);
// mode 1: plain fp32 write.
// ---------------------------------------------------------------------------
#define GS_OP   18432          // 128 rows * 144 B
#define GS_STG  (2*GS_OP)      // 36864 (A + B)
#define GS_SMEM (3*GS_STG)     // 110592

// scale const: D^-1/4 * sqrt(log2(e))
#define QK_SCALE 0.42466089786070306f

__device__ __forceinline__ void load_op64(
    uint32_t sdst, const __half* __restrict__ src, int Kdim, int k0, int tid)
{
#pragma unroll
    for (int p = 0; p < 8; p++) {
        int idx = tid + p * 128;        // 0..1023
        int row = idx >> 3;             // 0..127
        int c8  = (idx & 7) * 8;        // half col
        cp16(sdst + (uint32_t)(row * 144 + c8 * 2), src + (size_t)row * Kdim + k0 + c8);
    }
}

__global__ void __launch_bounds__(128, 2) gemm_f16_kernel(
    const __half* __restrict__ A, const __half* __restrict__ Bm,
    float* __restrict__ Cout, int Ndim, int Kdim, int mode,
    const float* __restrict__ w_std, const float* __restrict__ w_rec,
    const float* __restrict__ skip_std, const float* __restrict__ skip_low)
{
    extern __shared__ char smem[];
    const uint32_t sbase = smem_u32(smem);
    const int tid  = threadIdx.x;
    const int wid  = tid >> 5;
    const int lane = tid & 31;
    const int warp_m = wid >> 1;        // 0..1
    const int warp_n = wid & 1;         // 0..1

    const int m0 = blockIdx.y * 128;
    const int n0 = blockIdx.x * 128;

    const int lr = lane & 7, sel = lane >> 3;
    const int rowA = ((sel & 1) ? 8 : 0) + lr;
    const int kbA  = (sel & 2) ? 16 : 0;
    const int rowB = ((sel & 2) ? 8 : 0) + lr;
    const int kbB  = (sel & 1) ? 16 : 0;

    const uint32_t aoff = (uint32_t)((warp_m * 64 + rowA) * 144 + kbA);
    const uint32_t boff = (uint32_t)(GS_OP + (warp_n * 64 + rowB) * 144 + kbB);

    const __half* Ag = A  + (size_t)m0 * Kdim;
    const __half* Bg = Bm + (size_t)n0 * Kdim;

    float acc[4][8][4];
#pragma unroll
    for (int a = 0; a < 4; a++)
#pragma unroll
        for (int b = 0; b < 8; b++)
#pragma unroll
            for (int c = 0; c < 4; c++) acc[a][b][c] = 0.0f;

    const int nch = Kdim >> 6;          // BK=64

    load_op64(sbase,          Ag, Kdim, 0, tid);
    load_op64(sbase + GS_OP,  Bg, Kdim, 0, tid);
    asm volatile("cp.async.commit_group;" ::: "memory");
    load_op64(sbase + GS_STG,         Ag, Kdim, 64, tid);
    load_op64(sbase + GS_STG + GS_OP, Bg, Kdim, 64, tid);
    asm volatile("cp.async.commit_group;" ::: "memory");

    for (int i = 0; i < nch; i++) {
        if (i + 1 < nch) asm volatile("cp.async.wait_group 1;" ::: "memory");
        else             asm volatile("cp.async.wait_group 0;" ::: "memory");
        __syncthreads();
        if (i + 2 < nch) {
            const uint32_t st = sbase + (uint32_t)((i + 2) % 3) * GS_STG;
            load_op64(st,         Ag, Kdim, (i + 2) << 6, tid);
            load_op64(st + GS_OP, Bg, Kdim, (i + 2) << 6, tid);
            asm volatile("cp.async.commit_group;" ::: "memory");
        }
        const uint32_t sb = sbase + (uint32_t)(i % 3) * GS_STG;
#pragma unroll
        for (int ks = 0; ks < 4; ks++) {
            uint32_t a4[4][4], b4[4][4];
#pragma unroll
            for (int mt = 0; mt < 4; mt++)
                ldsm4(a4[mt], sb + aoff + (uint32_t)(mt * 2304 + ks * 32));
#pragma unroll
            for (int np = 0; np < 4; np++)
                ldsm4(b4[np], sb + boff + (uint32_t)(np * 2304 + ks * 32));
#pragma unroll
            for (int mt = 0; mt < 4; mt++)
#pragma unroll
                for (int nt = 0; nt < 8; nt++)
                    mma_f16(acc[mt][nt], a4[mt],
                            b4[nt >> 1][(nt & 1) * 2], b4[nt >> 1][(nt & 1) * 2 + 1]);
        }
    }

    // ----------------------------- epilogue --------------------------------
    const int lr4 = lane >> 2;
    const int lc2 = (lane & 3) * 2;

    if (mode == 0) {
        const int nb  = n0 + warp_n * 64;       // 64-aligned: exactly one head
        const int sec = nb >> 10;               // 0=q 1=k 2=v
        const int f   = nb & 1023;
        const int h   = f >> 6;
        float gstd = 1.0f, grec = 1.0f;
        if (sec < 2) {
            const float ss = sigmoidf_(skip_std[0]);
            const float sl = sigmoidf_(skip_low[0]);
            gstd = sqrtf(fmaxf(w_std[h] * ss, 1e-8f)) * QK_SCALE;
            grec = sqrtf(fmaxf(w_rec[h] * sl, 1e-8f)) * QK_SCALE;
        }
        __half* dst = (sec == 0) ? g_q16 : (sec == 1) ? g_k16 : g_v16;
#pragma unroll
        for (int mt = 0; mt < 4; mt++) {
            const int r0 = m0 + warp_m * 64 + mt * 16 + lr4;
#pragma unroll
            for (int half = 0; half < 2; half++) {
                const int m = r0 + half * 8;
                const int b = m >> 11;
                const int t = m & (T_ - 1);
                const size_t base = (((size_t)(b * H_ + h)) * T_ + t) * D_;
#pragma unroll
                for (int nt = 0; nt < 8; nt++) {
                    const int d = nt * 8 + lc2;
                    const float s0 = (sec < 2) ? ((d     < DSTD_) ? gstd : grec) : 1.0f;
                    const float s1 = (sec < 2) ? ((d + 1 < DSTD_) ? gstd : grec) : 1.0f;
                    uint32_t hv = packh2_(acc[mt][nt][half*2 + 0] * s0,
                                          acc[mt][nt][half*2 + 1] * s1);
                    *(uint32_t*)&dst[base + d] = hv;
                }
            }
        }
    } else {
#pragma unroll
        for (int mt = 0; mt < 4; mt++) {
            const int r0 = m0 + warp_m * 64 + mt * 16 + lr4;
#pragma unroll
            for (int half = 0; half < 2; half++) {
                const int m = r0 + half * 8;
#pragma unroll
                for (int nt = 0; nt < 8; nt++) {
                    const int col = n0 + warp_n * 64 + nt * 8 + lc2;
                    float2 o;
                    o.x = acc[mt][nt][half * 2 + 0];
                    o.y = acc[mt][nt][half * 2 + 1];
                    *(float2*)&Cout[(size_t)m * Ndim + col] = o;
                }
            }
        }
    }
}

// ---------------------------------------------------------------------------
// fp16 tensor-core causal flash attention + reciprocal mix.
// CTA: 8 warps, 128 q rows. KV tile = 64. 3-stage cp.async ring.
// Softmax: exp2 in f16x2; row-sum l via MMA against an ALL-ONES B fragment
// (every column of P.ones = rowsum -> every lane's c0/c2 holds l; this is
// the R6 NaN fix — col-0-only ones left 3/4 lanes with l=0).
// qt reversed so heaviest CTAs launch first.
// ---------------------------------------------------------------------------
#define AQ_B    18432               // Q region: 128*144
#define AT_T    9216                // one 64x144 tile
#define AT_STG2 (2*AT_T)            // K+V stage
#define AT_SMEM (AQ_B + 3*AT_STG2)  // 73728

__device__ __forceinline__ void attn_load_kv16(
    uint32_t sb, int k0, int tid,
    const __half* __restrict__ Kg, const __half* __restrict__ Vg)
{
#pragma unroll
    for (int p = 0; p < 2; p++) {
        int idx = tid + p * 256;    // 0..511
        int row = idx >> 3;         // 0..63
        int c8  = (idx & 7) * 8;
        cp16(sb + (uint32_t)(row * 144 + c8 * 2),        Kg + (size_t)(k0 + row) * 64 + c8);
        cp16(sb + (uint32_t)(AT_T + row * 144 + c8 * 2), Vg + (size_t)(k0 + row) * 64 + c8);
    }
}

__global__ void __launch_bounds__(256, 2) attn_f16_kernel(const float* __restrict__ rwr_alpha)
{
    extern __shared__ char smem[];
    const uint32_t sbase = smem_u32(smem);
    const int tid  = threadIdx.x;
    const int wid  = tid >> 5;
    const int lane = tid & 31;

    const int qt = (int)gridDim.x - 1 - (int)blockIdx.x;   // big tiles first
    const int bh = blockIdx.y;
    const int q0 = qt * 128;
    const int qw = q0 + wid * 16;

    const size_t hoff = (size_t)bh * (T_ * D_);
    const __half* Qg = g_q16 + hoff;
    const __half* Kg = g_k16 + hoff;
    const __half* Vg = g_v16 + hoff;

    // Q tile load (group 0)
#pragma unroll
    for (int p = 0; p < 4; p++) {
        int idx = tid + p * 256;
        int row = idx >> 3;
        int c8  = (idx & 7) * 8;
        cp16(sbase + (uint32_t)(row * 144 + c8 * 2), Qg + (size_t)(q0 + row) * 64 + c8);
    }
    asm volatile("cp.async.commit_group;" ::: "memory");

    const int nkt = 2 * qt + 2;

    attn_load_kv16(sbase + AQ_B,           0,  tid, Kg, Vg);
    asm volatile("cp.async.commit_group;" ::: "memory");
    attn_load_kv16(sbase + AQ_B + AT_STG2, 64, tid, Kg, Vg);
    asm volatile("cp.async.commit_group;" ::: "memory");

    asm volatile("cp.async.wait_group 2;" ::: "memory");
    __syncthreads();

    const int lr = lane & 7, sel = lane >> 3;
    const int rowA = ((sel & 1) ? 8 : 0) + lr;
    const int kbA  = (sel & 2) ? 16 : 0;
    const int rowB = ((sel & 2) ? 8 : 0) + lr;
    const int kbB  = (sel & 1) ? 16 : 0;

    uint32_t qh[4][4];
    {
        const uint32_t qaddr = sbase + (uint32_t)((wid * 16 + rowA) * 144 + kbA);
#pragma unroll
        for (int kc = 0; kc < 4; kc++) ldsm4(qh[kc], qaddr + (uint32_t)(kc * 32));
    }

    float O[8][4];
    float Ol[4] = {0.0f, 0.0f, 0.0f, 0.0f};     // c0 = l(row g), c2 = l(row g+8)
    float mrow[2] = {-1e30f, -1e30f};
#pragma unroll
    for (int nt = 0; nt < 8; nt++)
#pragma unroll
        for (int c = 0; c < 4; c++) O[nt][c] = 0.0f;

    const int g  = lane >> 2;
    const int t2 = (lane & 3) * 2;
    // ALL-ONES B fragment: every column of P.ones equals the row-sum, so
    // every lane's accumulator holds l. (Col-0-only version = R6 NaN bug.)
    const uint32_t ones = 0x3C003C00u;

    for (int kt = 0; kt < nkt; kt++) {
        if (kt + 1 < nkt) asm volatile("cp.async.wait_group 1;" ::: "memory");
        else              asm volatile("cp.async.wait_group 0;" ::: "memory");
        __syncthreads();
        if (kt + 2 < nkt) {
            attn_load_kv16(sbase + AQ_B + (uint32_t)((kt + 2) % 3) * AT_STG2,
                           (kt + 2) * 64, tid, Kg, Vg);
            asm volatile("cp.async.commit_group;" ::: "memory");
        }

        const uint32_t sb = sbase + AQ_B + (uint32_t)(kt % 3) * AT_STG2;
        const int k0 = kt * 64;

        if (k0 <= qw + 15) {
            // ---- S = Q.K^T (scores in log2 domain) ----
            float S[8][4];
#pragma unroll
            for (int nt = 0; nt < 8; nt++)
#pragma unroll
                for (int c = 0; c < 4; c++) S[nt][c] = 0.0f;

#pragma unroll
            for (int np = 0; np < 4; np++) {
                const uint32_t kb_ = sb + (uint32_t)((np * 16 + rowB) * 144 + kbB);
#pragma unroll
                for (int kc = 0; kc < 4; kc++) {
                    uint32_t k4[4];
                    ldsm4(k4, kb_ + (uint32_t)(kc * 32));
                    mma_f16(S[2*np],     qh[kc], k4[0], k4[1]);
                    mma_f16(S[2*np + 1], qh[kc], k4[2], k4[3]);
                }
            }

            // ---- causal mask ----
            if (k0 + 63 > qw) {
#pragma unroll
                for (int nt = 0; nt < 8; nt++) {
                    const int colb = k0 + nt * 8 + t2;
#pragma unroll
                    for (int c = 0; c < 2; c++) {
                        if (colb + c > qw + g)     S[nt][c]     = -1e30f;
                        if (colb + c > qw + g + 8) S[nt][2 + c] = -1e30f;
                    }
                }
            }

            // ---- online softmax: max + rescale (l comes from MMA) ----
            float mn[2];
#pragma unroll
            for (int r = 0; r < 2; r++) {
                float mx = -1e30f;
#pragma unroll
                for (int nt = 0; nt < 8; nt++)
                    mx = fmaxf(mx, fmaxf(S[nt][2*r], S[nt][2*r + 1]));
                mx = fmaxf(mx, __shfl_xor_sync(0xffffffffu, mx, 1));
                mx = fmaxf(mx, __shfl_xor_sync(0xffffffffu, mx, 2));
                mn[r] = fmaxf(mrow[r], mx);
                const float corr = ex2_(mrow[r] - mn[r]);
                mrow[r] = mn[r];
#pragma unroll
                for (int nt = 0; nt < 8; nt++) {
                    O[nt][2*r]     *= corr;
                    O[nt][2*r + 1] *= corr;
                }
                Ol[2*r] *= corr;
            }

            // ---- P = exp2(S - m) in f16x2 (P is fp16 for PV anyway) ----
            uint32_t pa[4][4];
#pragma unroll
            for (int kc = 0; kc < 4; kc++) {
                pa[kc][0] = ex2h2_(packh2_(S[2*kc][0]   - mn[0], S[2*kc][1]   - mn[0]));
                pa[kc][1] = ex2h2_(packh2_(S[2*kc][2]   - mn[1], S[2*kc][3]   - mn[1]));
                pa[kc][2] = ex2h2_(packh2_(S[2*kc+1][0] - mn[0], S[2*kc+1][1] - mn[0]));
                pa[kc][3] = ex2h2_(packh2_(S[2*kc+1][2] - mn[1], S[2*kc+1][3] - mn[1]));
            }

            // ---- O += P.V ; l += P.ones (same P, fp32 accum) ----
#pragma unroll
            for (int kc = 0; kc < 4; kc++) {
                mma_f16(Ol, pa[kc], ones, ones);
#pragma unroll
                for (int nd = 0; nd < 4; nd++) {
                    uint32_t v4[4];
                    const uint32_t vaddr = sb + (uint32_t)(AT_T
                        + (kc * 16 + (lane & 15)) * 144
                        + nd * 32 + ((lane & 16) ? 16 : 0));
                    ldsm4t(v4, vaddr);
                    mma_f16(O[2*nd],     pa[kc], v4[0], v4[1]);
                    mma_f16(O[2*nd + 1], pa[kc], v4[2], v4[3]);
                }
            }
        }
    }

    // ---- epilogue: normalize, reciprocal mix, write y fp16 ----
    const int h = bh & (H_ - 1);
    const int b = bh >> 4;
    const float alpha = fminf(fmaxf(rwr_alpha[h], 0.0f), 0.5f);
    const float om = 1.0f - alpha;

#pragma unroll
    for (int r = 0; r < 2; r++) {
        const int q = qw + g + r * 8;
        const float inv = 1.0f / Ol[2*r];
        const size_t vrow = (size_t)q * 64;
        const size_t orow = ((size_t)(b * T_ + q)) * C_ + h * 64;
#pragma unroll
        for (int nt = 0; nt < 8; nt++) {
            const int d = nt * 8 + t2;
            const uint32_t uv = *(const uint32_t*)&Vg[vrow + d];
            const float2 fv = __half22float2(*(const __half2*)&uv);
            const float y0 = om * (O[nt][2*r]     * inv) + alpha * fv.x;
            const float y1 = om * (O[nt][2*r + 1] * inv) + alpha * fv.y;
            *(uint32_t*)&g_y16[orow + d] = packh2_(y0, y1);
        }
    }
}

// ---------------------------------------------------------------------------
extern "C" void kernel_launch(void* const* d_in, const int* in_sizes, int n_in,
                              void* d_out, int out_size)
{
    const float* x         = (const float*)d_in[0];
    const float* W_attn    = (const float*)d_in[1];
    const float* W_proj    = (const float*)d_in[2];
    const float* w_std     = (const float*)d_in[3];
    const float* w_rec     = (const float*)d_in[4];
    const float* skip_std  = (const float*)d_in[5];
    const float* skip_low  = (const float*)d_in[6];
    const float* rwr_alpha = (const float*)d_in[7];
    float* out = (float*)d_out;

    static void *p_x16 = nullptr, *p_wa16, *p_wp16, *p_y16;
    if (!p_x16) {
        cudaGetSymbolAddress(&p_x16,  g_x16);
        cudaGetSymbolAddress(&p_wa16, g_wa16);
        cudaGetSymbolAddress(&p_wp16, g_wp16);
        cudaGetSymbolAddress(&p_y16,  g_y16);
    }

    static bool attr_set = false;
    if (!attr_set) {
        cudaFuncSetAttribute(gemm_f16_kernel, cudaFuncAttributeMaxDynamicSharedMemorySize, GS_SMEM);
        cudaFuncSetAttribute(attn_f16_kernel, cudaFuncAttributeMaxDynamicSharedMemorySize, AT_SMEM);
        attr_set = true;
    }

    // 1. fused fp32 -> fp16 conversion (x, W_attn, W_proj)
    conv_kernel<<<(NTOT4_ + 255) / 256, 256>>>(
        (const float4*)x, (const float4*)W_attn, (const float4*)W_proj);

    // 2. QKV GEMM -> q/k/v fp16 with head scaling (+ log2e fold for q,k)
    gemm_f16_kernel<<<dim3(3*C_/128, M_/128), 128, GS_SMEM>>>(
        (const __half*)p_x16, (const __half*)p_wa16,
        nullptr, 3*C_, C_, 0, w_std, w_rec, skip_std, skip_low);

    // 3. fp16 tensor-core causal attention + reciprocal mix -> y fp16
    attn_f16_kernel<<<dim3(T_/128, B_*H_), 256, AT_SMEM>>>(rwr_alpha);

    // 4. output projection -> fp32 out
    gemm_f16_kernel<<<dim3(C_/128, M_/128), 128, GS_SMEM>>>(
        (const __half*)p_y16, (const __half*)p_wp16,
        out, C_, C_, 1, nullptr, nullptr, nullptr, nullptr);
}

// round 9
// speedup vs baseline: 8.9810x; 1.0315x over previous
#include <cuda_runtime.h>
#include <cuda_fp16.h>
#include <cstdint>
#include <math.h>

// Problem constants
#define B_    2
#define T_    2048
#define C_    1024
#define H_    16
#define D_    64
#define DSTD_ 60
#define M_    (B_*T_)   // 4096 rows

// ---------------------------------------------------------------------------
// Scratch (__device__ globals; no allocation allowed)
// ---------------------------------------------------------------------------
__device__ __half g_x16[M_*C_];
__device__ __half g_wa16[3*C_*C_];
__device__ __half g_wp16[C_*C_];
__device__ __half g_y16[M_*C_];
__device__ __half g_q16[B_*H_*T_*D_];   // [B*H, T, D]
__device__ __half g_k16[B_*H_*T_*D_];
__device__ __half g_v16[B_*H_*T_*D_];

__device__ __forceinline__ float sigmoidf_(float v) { return 1.0f / (1.0f + __expf(-v)); }

__device__ __forceinline__ uint32_t smem_u32(const void* p) {
    return (uint32_t)__cvta_generic_to_shared(p);
}

__device__ __forceinline__ float ex2_(float x) {
    float r; asm("ex2.approx.f32 %0, %1;" : "=f"(r) : "f"(x)); return r;
}
__device__ __forceinline__ uint32_t ex2h2_(uint32_t x) {
    uint32_t r; asm("ex2.approx.f16x2 %0, %1;" : "=r"(r) : "r"(x)); return r;
}
__device__ __forceinline__ uint32_t packh2_(float x, float y) {
    __half2 h = __floats2half2_rn(x, y);
    return *reinterpret_cast<uint32_t*>(&h);
}

// ---------------------------------------------------------------------------
// warp-mma helpers (baseline PTX ISA — safe for compute_103 target)
// ---------------------------------------------------------------------------
__device__ __forceinline__ void ldsm4(uint32_t* r, uint32_t addr) {
    asm volatile("ldmatrix.sync.aligned.m8n8.x4.shared.b16 {%0,%1,%2,%3}, [%4];"
        : "=r"(r[0]), "=r"(r[1]), "=r"(r[2]), "=r"(r[3]) : "r"(addr));
}

__device__ __forceinline__ void ldsm4t(uint32_t* r, uint32_t addr) {
    asm volatile("ldmatrix.sync.aligned.m8n8.x4.trans.shared.b16 {%0,%1,%2,%3}, [%4];"
        : "=r"(r[0]), "=r"(r[1]), "=r"(r[2]), "=r"(r[3]) : "r"(addr));
}

__device__ __forceinline__ void mma_f16(float* c, const uint32_t* a, uint32_t b0, uint32_t b1) {
    asm volatile("mma.sync.aligned.m16n8k16.row.col.f32.f16.f16.f32 "
        "{%0,%1,%2,%3}, {%4,%5,%6,%7}, {%8,%9}, {%0,%1,%2,%3};"
        : "+f"(c[0]), "+f"(c[1]), "+f"(c[2]), "+f"(c[3])
        : "r"(a[0]), "r"(a[1]), "r"(a[2]), "r"(a[3]), "r"(b0), "r"(b1));
}

__device__ __forceinline__ void cp16(uint32_t saddr, const void* gaddr) {
    asm volatile("cp.async.cg.shared.global [%0], [%1], 16;" :: "r"(saddr), "l"(gaddr));
}

// ---------------------------------------------------------------------------
// fused fp32 -> fp16 convert for x, W_attn, W_proj (one launch)
// ---------------------------------------------------------------------------
#define NX4_  (M_*C_/4)       // 1048576
#define NWA4_ (3*C_*C_/4)     // 786432
#define NWP4_ (C_*C_/4)       // 262144
#define NTOT4_ (NX4_+NWA4_+NWP4_)

__global__ __launch_bounds__(256) void conv_kernel(
    const float4* __restrict__ x, const float4* __restrict__ wa, const float4* __restrict__ wp)
{
    int i = blockIdx.x * blockDim.x + threadIdx.x;
    if (i >= NTOT4_) return;
    const float4* s; uint2* d; int o;
    if (i < NX4_)              { s = x;  d = (uint2*)g_x16;  o = i; }
    else if (i < NX4_ + NWA4_) { s = wa; d = (uint2*)g_wa16; o = i - NX4_; }
    else                       { s = wp; d = (uint2*)g_wp16; o = i - NX4_ - NWA4_; }
    float4 v = s[o];
    d[o] = make_uint2(packh2_(v.x, v.y), packh2_(v.z, v.w));
}

// ---------------------------------------------------------------------------
// fp16 warp-MMA GEMM (NT): C[m,n] = sum_k A[m,k]*B[n,k].
// CTA 128x128, 128 threads, 4 warps as 2(m) x 2(n) -> 64x64 per warp.
// BK=32, 4-stage cp.async ring (prefetch distance 3), ONE barrier per chunk.
// ACC-MAJOR MMA ORDER: each accumulator gets a dependent chain of 2 MMAs
// (ks=0,1) back-to-back — tests the RF operand-churn hypothesis (R3's
// same-acc bursts hit 52.9% tensor busy vs 41-42% for acc-cycling orders).
// mode 0: scatter q/k/v fp16 with head scaling; mode 1: plain fp32 write.
// ---------------------------------------------------------------------------
#define GS_OP   10240          // 128 rows * 80 B
#define GS_STG  (2*GS_OP)      // 20480 (A + B)
#define GS_SMEM (4*GS_STG)     // 81920

// scale const: D^-1/4 * sqrt(log2(e))
#define QK_SCALE 0.42466089786070306f

__device__ __forceinline__ void load_op32(
    uint32_t sdst, const __half* __restrict__ src, int Kdim, int k0, int tid)
{
#pragma unroll
    for (int p = 0; p < 4; p++) {
        int idx = tid + p * 128;        // 0..511
        int row = idx >> 2;             // 0..127
        int c8  = (idx & 3) * 8;        // half col 0..24
        cp16(sdst + (uint32_t)(row * 80 + c8 * 2), src + (size_t)row * Kdim + k0 + c8);
    }
}

__global__ void __launch_bounds__(128, 2) gemm_f16_kernel(
    const __half* __restrict__ A, const __half* __restrict__ Bm,
    float* __restrict__ Cout, int Ndim, int Kdim, int mode,
    const float* __restrict__ w_std, const float* __restrict__ w_rec,
    const float* __restrict__ skip_std, const float* __restrict__ skip_low)
{
    extern __shared__ char smem[];
    const uint32_t sbase = smem_u32(smem);
    const int tid  = threadIdx.x;
    const int wid  = tid >> 5;
    const int lane = tid & 31;
    const int warp_m = wid >> 1;        // 0..1
    const int warp_n = wid & 1;         // 0..1

    const int m0 = blockIdx.y * 128;
    const int n0 = blockIdx.x * 128;

    const int lr = lane & 7, sel = lane >> 3;
    const int rowA = ((sel & 1) ? 8 : 0) + lr;
    const int kbA  = (sel & 2) ? 16 : 0;
    const int rowB = ((sel & 2) ? 8 : 0) + lr;
    const int kbB  = (sel & 1) ? 16 : 0;

    const uint32_t aoff = (uint32_t)((warp_m * 64 + rowA) * 80 + kbA);
    const uint32_t boff = (uint32_t)(GS_OP + (warp_n * 64 + rowB) * 80 + kbB);

    const __half* Ag = A  + (size_t)m0 * Kdim;
    const __half* Bg = Bm + (size_t)n0 * Kdim;

    float acc[4][8][4];
#pragma unroll
    for (int a = 0; a < 4; a++)
#pragma unroll
        for (int b = 0; b < 8; b++)
#pragma unroll
            for (int c = 0; c < 4; c++) acc[a][b][c] = 0.0f;

    const int nch = Kdim >> 5;          // BK=32

    // prologue: chunks 0,1,2 into stages 0,1,2
#pragma unroll
    for (int pc = 0; pc < 3; pc++) {
        const uint32_t st = sbase + (uint32_t)pc * GS_STG;
        load_op32(st,         Ag, Kdim, pc << 5, tid);
        load_op32(st + GS_OP, Bg, Kdim, pc << 5, tid);
        asm volatile("cp.async.commit_group;" ::: "memory");
    }

    for (int i = 0; i < nch; i++) {
        if (i + 3 < nch)      asm volatile("cp.async.wait_group 2;" ::: "memory");
        else if (i + 2 < nch) asm volatile("cp.async.wait_group 2;" ::: "memory");
        else if (i + 1 < nch) asm volatile("cp.async.wait_group 1;" ::: "memory");
        else                  asm volatile("cp.async.wait_group 0;" ::: "memory");
        __syncthreads();
        if (i + 3 < nch) {
            const uint32_t st = sbase + (uint32_t)((i + 3) & 3) * GS_STG;
            load_op32(st,         Ag, Kdim, (i + 3) << 5, tid);
            load_op32(st + GS_OP, Bg, Kdim, (i + 3) << 5, tid);
            asm volatile("cp.async.commit_group;" ::: "memory");
        }
        const uint32_t sb = sbase + (uint32_t)(i & 3) * GS_STG;

        // load BOTH ks frag sets, then issue MMAs acc-major (chains of 2)
        uint32_t a4[2][4][4], b4[2][4][4];
#pragma unroll
        for (int ks = 0; ks < 2; ks++) {
#pragma unroll
            for (int mt = 0; mt < 4; mt++)
                ldsm4(a4[ks][mt], sb + aoff + (uint32_t)(mt * 1280 + ks * 32));
#pragma unroll
            for (int np = 0; np < 4; np++)
                ldsm4(b4[ks][np], sb + boff + (uint32_t)(np * 1280 + ks * 32));
        }
#pragma unroll
        for (int mt = 0; mt < 4; mt++)
#pragma unroll
            for (int nt = 0; nt < 8; nt++) {
                const int np = nt >> 1, h = (nt & 1) * 2;
                mma_f16(acc[mt][nt], a4[0][mt], b4[0][np][h], b4[0][np][h + 1]);
                mma_f16(acc[mt][nt], a4[1][mt], b4[1][np][h], b4[1][np][h + 1]);
            }
    }

    // ----------------------------- epilogue --------------------------------
    const int lr4 = lane >> 2;
    const int lc2 = (lane & 3) * 2;

    if (mode == 0) {
        const int nb  = n0 + warp_n * 64;       // 64-aligned: exactly one head
        const int sec = nb >> 10;               // 0=q 1=k 2=v
        const int f   = nb & 1023;
        const int h   = f >> 6;
        float gstd = 1.0f, grec = 1.0f;
        if (sec < 2) {
            const float ss = sigmoidf_(skip_std[0]);
            const float sl = sigmoidf_(skip_low[0]);
            gstd = sqrtf(fmaxf(w_std[h] * ss, 1e-8f)) * QK_SCALE;
            grec = sqrtf(fmaxf(w_rec[h] * sl, 1e-8f)) * QK_SCALE;
        }
        __half* dst = (sec == 0) ? g_q16 : (sec == 1) ? g_k16 : g_v16;
#pragma unroll
        for (int mt = 0; mt < 4; mt++) {
            const int r0 = m0 + warp_m * 64 + mt * 16 + lr4;
#pragma unroll
            for (int half = 0; half < 2; half++) {
                const int m = r0 + half * 8;
                const int b = m >> 11;
                const int t = m & (T_ - 1);
                const size_t base = (((size_t)(b * H_ + h)) * T_ + t) * D_;
#pragma unroll
                for (int nt = 0; nt < 8; nt++) {
                    const int d = nt * 8 + lc2;
                    const float s0 = (sec < 2) ? ((d     < DSTD_) ? gstd : grec) : 1.0f;
                    const float s1 = (sec < 2) ? ((d + 1 < DSTD_) ? gstd : grec) : 1.0f;
                    uint32_t hv = packh2_(acc[mt][nt][half*2 + 0] * s0,
                                          acc[mt][nt][half*2 + 1] * s1);
                    *(uint32_t*)&dst[base + d] = hv;
                }
            }
        }
    } else {
#pragma unroll
        for (int mt = 0; mt < 4; mt++) {
            const int r0 = m0 + warp_m * 64 + mt * 16 + lr4;
#pragma unroll
            for (int half = 0; half < 2; half++) {
                const int m = r0 + half * 8;
#pragma unroll
                for (int nt = 0; nt < 8; nt++) {
                    const int col = n0 + warp_n * 64 + nt * 8 + lc2;
                    float2 o;
                    o.x = acc[mt][nt][half * 2 + 0];
                    o.y = acc[mt][nt][half * 2 + 1];
                    *(float2*)&Cout[(size_t)m * Ndim + col] = o;
                }
            }
        }
    }
}

// ---------------------------------------------------------------------------
// fp16 tensor-core causal flash attention + reciprocal mix. (unchanged R8)
// ---------------------------------------------------------------------------
#define AQ_B    18432               // Q region: 128*144
#define AT_T    9216                // one 64x144 tile
#define AT_STG2 (2*AT_T)            // K+V stage
#define AT_SMEM (AQ_B + 3*AT_STG2)  // 73728

__device__ __forceinline__ void attn_load_kv16(
    uint32_t sb, int k0, int tid,
    const __half* __restrict__ Kg, const __half* __restrict__ Vg)
{
#pragma unroll
    for (int p = 0; p < 2; p++) {
        int idx = tid + p * 256;    // 0..511
        int row = idx >> 3;         // 0..63
        int c8  = (idx & 7) * 8;
        cp16(sb + (uint32_t)(row * 144 + c8 * 2),        Kg + (size_t)(k0 + row) * 64 + c8);
        cp16(sb + (uint32_t)(AT_T + row * 144 + c8 * 2), Vg + (size_t)(k0 + row) * 64 + c8);
    }
}

__global__ void __launch_bounds__(256, 2) attn_f16_kernel(const float* __restrict__ rwr_alpha)
{
    extern __shared__ char smem[];
    const uint32_t sbase = smem_u32(smem);
    const int tid  = threadIdx.x;
    const int wid  = tid >> 5;
    const int lane = tid & 31;

    const int qt = (int)gridDim.x - 1 - (int)blockIdx.x;   // big tiles first
    const int bh = blockIdx.y;
    const int q0 = qt * 128;
    const int qw = q0 + wid * 16;

    const size_t hoff = (size_t)bh * (T_ * D_);
    const __half* Qg = g_q16 + hoff;
    const __half* Kg = g_k16 + hoff;
    const __half* Vg = g_v16 + hoff;

    // Q tile load (group 0)
#pragma unroll
    for (int p = 0; p < 4; p++) {
        int idx = tid + p * 256;
        int row = idx >> 3;
        int c8  = (idx & 7) * 8;
        cp16(sbase + (uint32_t)(row * 144 + c8 * 2), Qg + (size_t)(q0 + row) * 64 + c8);
    }
    asm volatile("cp.async.commit_group;" ::: "memory");

    const int nkt = 2 * qt + 2;

    attn_load_kv16(sbase + AQ_B,           0,  tid, Kg, Vg);
    asm volatile("cp.async.commit_group;" ::: "memory");
    attn_load_kv16(sbase + AQ_B + AT_STG2, 64, tid, Kg, Vg);
    asm volatile("cp.async.commit_group;" ::: "memory");

    asm volatile("cp.async.wait_group 2;" ::: "memory");
    __syncthreads();

    const int lr = lane & 7, sel = lane >> 3;
    const int rowA = ((sel & 1) ? 8 : 0) + lr;
    const int kbA  = (sel & 2) ? 16 : 0;
    const int rowB = ((sel & 2) ? 8 : 0) + lr;
    const int kbB  = (sel & 1) ? 16 : 0;

    uint32_t qh[4][4];
    {
        const uint32_t qaddr = sbase + (uint32_t)((wid * 16 + rowA) * 144 + kbA);
#pragma unroll
        for (int kc = 0; kc < 4; kc++) ldsm4(qh[kc], qaddr + (uint32_t)(kc * 32));
    }

    float O[8][4];
    float Ol[4] = {0.0f, 0.0f, 0.0f, 0.0f};     // c0 = l(row g), c2 = l(row g+8)
    float mrow[2] = {-1e30f, -1e30f};
#pragma unroll
    for (int nt = 0; nt < 8; nt++)
#pragma unroll
        for (int c = 0; c < 4; c++) O[nt][c] = 0.0f;

    const int g  = lane >> 2;
    const int t2 = (lane & 3) * 2;
    // ALL-ONES B fragment: every column of P.ones equals the row-sum.
    const uint32_t ones = 0x3C003C00u;

    for (int kt = 0; kt < nkt; kt++) {
        if (kt + 1 < nkt) asm volatile("cp.async.wait_group 1;" ::: "memory");
        else              asm volatile("cp.async.wait_group 0;" ::: "memory");
        __syncthreads();
        if (kt + 2 < nkt) {
            attn_load_kv16(sbase + AQ_B + (uint32_t)((kt + 2) % 3) * AT_STG2,
                           (kt + 2) * 64, tid, Kg, Vg);
            asm volatile("cp.async.commit_group;" ::: "memory");
        }

        const uint32_t sb = sbase + AQ_B + (uint32_t)(kt % 3) * AT_STG2;
        const int k0 = kt * 64;

        if (k0 <= qw + 15) {
            // ---- S = Q.K^T (scores in log2 domain) ----
            float S[8][4];
#pragma unroll
            for (int nt = 0; nt < 8; nt++)
#pragma unroll
                for (int c = 0; c < 4; c++) S[nt][c] = 0.0f;

#pragma unroll
            for (int np = 0; np < 4; np++) {
                const uint32_t kb_ = sb + (uint32_t)((np * 16 + rowB) * 144 + kbB);
#pragma unroll
                for (int kc = 0; kc < 4; kc++) {
                    uint32_t k4[4];
                    ldsm4(k4, kb_ + (uint32_t)(kc * 32));
                    mma_f16(S[2*np],     qh[kc], k4[0], k4[1]);
                    mma_f16(S[2*np + 1], qh[kc], k4[2], k4[3]);
                }
            }

            // ---- causal mask ----
            if (k0 + 63 > qw) {
#pragma unroll
                for (int nt = 0; nt < 8; nt++) {
                    const int colb = k0 + nt * 8 + t2;
#pragma unroll
                    for (int c = 0; c < 2; c++) {
                        if (colb + c > qw + g)     S[nt][c]     = -1e30f;
                        if (colb + c > qw + g + 8) S[nt][2 + c] = -1e30f;
                    }
                }
            }

            // ---- online softmax: max + rescale (l comes from MMA) ----
            float mn[2];
#pragma unroll
            for (int r = 0; r < 2; r++) {
                float mx = -1e30f;
#pragma unroll
                for (int nt = 0; nt < 8; nt++)
                    mx = fmaxf(mx, fmaxf(S[nt][2*r], S[nt][2*r + 1]));
                mx = fmaxf(mx, __shfl_xor_sync(0xffffffffu, mx, 1));
                mx = fmaxf(mx, __shfl_xor_sync(0xffffffffu, mx, 2));
                mn[r] = fmaxf(mrow[r], mx);
                const float corr = ex2_(mrow[r] - mn[r]);
                mrow[r] = mn[r];
#pragma unroll
                for (int nt = 0; nt < 8; nt++) {
                    O[nt][2*r]     *= corr;
                    O[nt][2*r + 1] *= corr;
                }
                Ol[2*r] *= corr;
            }

            // ---- P = exp2(S - m) in f16x2 ----
            uint32_t pa[4][4];
#pragma unroll
            for (int kc = 0; kc < 4; kc++) {
                pa[kc][0] = ex2h2_(packh2_(S[2*kc][0]   - mn[0], S[2*kc][1]   - mn[0]));
                pa[kc][1] = ex2h2_(packh2_(S[2*kc][2]   - mn[1], S[2*kc][3]   - mn[1]));
                pa[kc][2] = ex2h2_(packh2_(S[2*kc+1][0] - mn[0], S[2*kc+1][1] - mn[0]));
                pa[kc][3] = ex2h2_(packh2_(S[2*kc+1][2] - mn[1], S[2*kc+1][3] - mn[1]));
            }

            // ---- O += P.V ; l += P.ones (same P, fp32 accum) ----
#pragma unroll
            for (int kc = 0; kc < 4; kc++) {
                mma_f16(Ol, pa[kc], ones, ones);
#pragma unroll
                for (int nd = 0; nd < 4; nd++) {
                    uint32_t v4[4];
                    const uint32_t vaddr = sb + (uint32_t)(AT_T
                        + (kc * 16 + (lane & 15)) * 144
                        + nd * 32 + ((lane & 16) ? 16 : 0));
                    ldsm4t(v4, vaddr);
                    mma_f16(O[2*nd],     pa[kc], v4[0], v4[1]);
                    mma_f16(O[2*nd + 1], pa[kc], v4[2], v4[3]);
                }
            }
        }
    }

    // ---- epilogue: normalize, reciprocal mix, write y fp16 ----
    const int h = bh & (H_ - 1);
    const int b = bh >> 4;
    const float alpha = fminf(fmaxf(rwr_alpha[h], 0.0f), 0.5f);
    const float om = 1.0f - alpha;

#pragma unroll
    for (int r = 0; r < 2; r++) {
        const int q = qw + g + r * 8;
        const float inv = 1.0f / Ol[2*r];
        const size_t vrow = (size_t)q * 64;
        const size_t orow = ((size_t)(b * T_ + q)) * C_ + h * 64;
#pragma unroll
        for (int nt = 0; nt < 8; nt++) {
            const int d = nt * 8 + t2;
            const uint32_t uv = *(const uint32_t*)&Vg[vrow + d];
            const float2 fv = __half22float2(*(const __half2*)&uv);
            const float y0 = om * (O[nt][2*r]     * inv) + alpha * fv.x;
            const float y1 = om * (O[nt][2*r + 1] * inv) + alpha * fv.y;
            *(uint32_t*)&g_y16[orow + d] = packh2_(y0, y1);
        }
    }
}

// ---------------------------------------------------------------------------
extern "C" void kernel_launch(void* const* d_in, const int* in_sizes, int n_in,
                              void* d_out, int out_size)
{
    const float* x         = (const float*)d_in[0];
    const float* W_attn    = (const float*)d_in[1];
    const float* W_proj    = (const float*)d_in[2];
    const float* w_std     = (const float*)d_in[3];
    const float* w_rec     = (const float*)d_in[4];
    const float* skip_std  = (const float*)d_in[5];
    const float* skip_low  = (const float*)d_in[6];
    const float* rwr_alpha = (const float*)d_in[7];
    float* out = (float*)d_out;

    static void *p_x16 = nullptr, *p_wa16, *p_wp16, *p_y16;
    if (!p_x16) {
        cudaGetSymbolAddress(&p_x16,  g_x16);
        cudaGetSymbolAddress(&p_wa16, g_wa16);
        cudaGetSymbolAddress(&p_wp16, g_wp16);
        cudaGetSymbolAddress(&p_y16,  g_y16);
    }

    static bool attr_set = false;
    if (!attr_set) {
        cudaFuncSetAttribute(gemm_f16_kernel, cudaFuncAttributeMaxDynamicSharedMemorySize, GS_SMEM);
        cudaFuncSetAttribute(attn_f16_kernel, cudaFuncAttributeMaxDynamicSharedMemorySize, AT_SMEM);
        attr_set = true;
    }

    // 1. fused fp32 -> fp16 conversion (x, W_attn, W_proj)
    conv_kernel<<<(NTOT4_ + 255) / 256, 256>>>(
        (const float4*)x, (const float4*)W_attn, (const float4*)W_proj);

    // 2. QKV GEMM -> q/k/v fp16 with head scaling (+ log2e fold for q,k)
    gemm_f16_kernel<<<dim3(3*C_/128, M_/128), 128, GS_SMEM>>>(
        (const __half*)p_x16, (const __half*)p_wa16,
        nullptr, 3*C_, C_, 0, w_std, w_rec, skip_std, skip_low);

    // 3. fp16 tensor-core causal attention + reciprocal mix -> y fp16
    attn_f16_kernel<<<dim3(T_/128, B_*H_), 256, AT_SMEM>>>(rwr_alpha);

    // 4. output projection -> fp32 out
    gemm_f16_kernel<<<dim3(C_/128, M_/128), 128, GS_SMEM>>>(
        (const __half*)p_y16, (const __half*)p_wp16,
        out, C_, C_, 1, nullptr, nullptr, nullptr, nullptr);
}

// round 12
// speedup vs baseline: 9.6078x; 1.0698x over previous
#include <cuda_runtime.h>
#include <cuda_fp16.h>
#include <cstdint>
#include <math.h>

// Problem constants
#define B_    2
#define T_    2048
#define C_    1024
#define H_    16
#define D_    64
#define DSTD_ 60
#define M_    (B_*T_)   // 4096 rows

// ---------------------------------------------------------------------------
// Scratch (__device__ globals; no allocation allowed)
// ---------------------------------------------------------------------------
__device__ __half g_x16[M_*C_];
__device__ __half g_wa16[3*C_*C_];
__device__ __half g_wp16[C_*C_];
__device__ __half g_y16[M_*C_];
__device__ __half g_q16[B_*H_*T_*D_];   // [B*H, T, D]
__device__ __half g_k16[B_*H_*T_*D_];
__device__ __half g_v16[B_*H_*T_*D_];

__device__ __forceinline__ float sigmoidf_(float v) { return 1.0f / (1.0f + __expf(-v)); }

__device__ __forceinline__ uint32_t smem_u32(const void* p) {
    return (uint32_t)__cvta_generic_to_shared(p);
}

__device__ __forceinline__ float ex2_(float x) {
    float r; asm("ex2.approx.f32 %0, %1;" : "=f"(r) : "f"(x)); return r;
}
__device__ __forceinline__ uint32_t ex2h2_(uint32_t x) {
    uint32_t r; asm("ex2.approx.f16x2 %0, %1;" : "=r"(r) : "r"(x)); return r;
}
__device__ __forceinline__ uint32_t packh2_(float x, float y) {
    __half2 h = __floats2half2_rn(x, y);
    return *reinterpret_cast<uint32_t*>(&h);
}

// ---------------------------------------------------------------------------
// warp-mma helpers (baseline PTX ISA — safe for compute_103 target)
// ---------------------------------------------------------------------------
__device__ __forceinline__ void ldsm4(uint32_t* r, uint32_t addr) {
    asm volatile("ldmatrix.sync.aligned.m8n8.x4.shared.b16 {%0,%1,%2,%3}, [%4];"
        : "=r"(r[0]), "=r"(r[1]), "=r"(r[2]), "=r"(r[3]) : "r"(addr));
}

__device__ __forceinline__ void ldsm4t(uint32_t* r, uint32_t addr) {
    asm volatile("ldmatrix.sync.aligned.m8n8.x4.trans.shared.b16 {%0,%1,%2,%3}, [%4];"
        : "=r"(r[0]), "=r"(r[1]), "=r"(r[2]), "=r"(r[3]) : "r"(addr));
}

__device__ __forceinline__ void mma_f16(float* c, const uint32_t* a, uint32_t b0, uint32_t b1) {
    asm volatile("mma.sync.aligned.m16n8k16.row.col.f32.f16.f16.f32 "
        "{%0,%1,%2,%3}, {%4,%5,%6,%7}, {%8,%9}, {%0,%1,%2,%3};"
        : "+f"(c[0]), "+f"(c[1]), "+f"(c[2]), "+f"(c[3])
        : "r"(a[0]), "r"(a[1]), "r"(a[2]), "r"(a[3]), "r"(b0), "r"(b1));
}

__device__ __forceinline__ void cp16(uint32_t saddr, const void* gaddr) {
    asm volatile("cp.async.cg.shared.global [%0], [%1], 16;" :: "r"(saddr), "l"(gaddr));
}

// ---------------------------------------------------------------------------
// fused fp32 -> fp16 convert for x, W_attn, W_proj (one launch)
// ---------------------------------------------------------------------------
#define NX4_  (M_*C_/4)       // 1048576
#define NWA4_ (3*C_*C_/4)     // 786432
#define NWP4_ (C_*C_/4)       // 262144
#define NTOT4_ (NX4_+NWA4_+NWP4_)

__global__ __launch_bounds__(256) void conv_kernel(
    const float4* __restrict__ x, const float4* __restrict__ wa, const float4* __restrict__ wp)
{
    int i = blockIdx.x * blockDim.x + threadIdx.x;
    if (i >= NTOT4_) return;
    const float4* s; uint2* d; int o;
    if (i < NX4_)              { s = x;  d = (uint2*)g_x16;  o = i; }
    else if (i < NX4_ + NWA4_) { s = wa; d = (uint2*)g_wa16; o = i - NX4_; }
    else                       { s = wp; d = (uint2*)g_wp16; o = i - NX4_ - NWA4_; }
    float4 v = s[o];
    d[o] = make_uint2(packh2_(v.x, v.y), packh2_(v.z, v.w));
}

// ---------------------------------------------------------------------------
// fp16 warp-MMA GEMM (NT) — unchanged from R9 (acc-major, BK=32, 4-stage).
// ---------------------------------------------------------------------------
#define GS_OP   10240          // 128 rows * 80 B
#define GS_STG  (2*GS_OP)      // 20480 (A + B)
#define GS_SMEM (4*GS_STG)     // 81920

// scale const: D^-1/4 * sqrt(log2(e))
#define QK_SCALE 0.42466089786070306f

__device__ __forceinline__ void load_op32(
    uint32_t sdst, const __half* __restrict__ src, int Kdim, int k0, int tid)
{
#pragma unroll
    for (int p = 0; p < 4; p++) {
        int idx = tid + p * 128;        // 0..511
        int row = idx >> 2;             // 0..127
        int c8  = (idx & 3) * 8;        // half col 0..24
        cp16(sdst + (uint32_t)(row * 80 + c8 * 2), src + (size_t)row * Kdim + k0 + c8);
    }
}

__global__ void __launch_bounds__(128, 2) gemm_f16_kernel(
    const __half* __restrict__ A, const __half* __restrict__ Bm,
    float* __restrict__ Cout, int Ndim, int Kdim, int mode,
    const float* __restrict__ w_std, const float* __restrict__ w_rec,
    const float* __restrict__ skip_std, const float* __restrict__ skip_low)
{
    extern __shared__ char smem[];
    const uint32_t sbase = smem_u32(smem);
    const int tid  = threadIdx.x;
    const int wid  = tid >> 5;
    const int lane = tid & 31;
    const int warp_m = wid >> 1;        // 0..1
    const int warp_n = wid & 1;         // 0..1

    const int m0 = blockIdx.y * 128;
    const int n0 = blockIdx.x * 128;

    const int lr = lane & 7, sel = lane >> 3;
    const int rowA = ((sel & 1) ? 8 : 0) + lr;
    const int kbA  = (sel & 2) ? 16 : 0;
    const int rowB = ((sel & 2) ? 8 : 0) + lr;
    const int kbB  = (sel & 1) ? 16 : 0;

    const uint32_t aoff = (uint32_t)((warp_m * 64 + rowA) * 80 + kbA);
    const uint32_t boff = (uint32_t)(GS_OP + (warp_n * 64 + rowB) * 80 + kbB);

    const __half* Ag = A  + (size_t)m0 * Kdim;
    const __half* Bg = Bm + (size_t)n0 * Kdim;

    float acc[4][8][4];
#pragma unroll
    for (int a = 0; a < 4; a++)
#pragma unroll
        for (int b = 0; b < 8; b++)
#pragma unroll
            for (int c = 0; c < 4; c++) acc[a][b][c] = 0.0f;

    const int nch = Kdim >> 5;          // BK=32

#pragma unroll
    for (int pc = 0; pc < 3; pc++) {
        const uint32_t st = sbase + (uint32_t)pc * GS_STG;
        load_op32(st,         Ag, Kdim, pc << 5, tid);
        load_op32(st + GS_OP, Bg, Kdim, pc << 5, tid);
        asm volatile("cp.async.commit_group;" ::: "memory");
    }

    for (int i = 0; i < nch; i++) {
        if (i + 2 < nch)      asm volatile("cp.async.wait_group 2;" ::: "memory");
        else if (i + 1 < nch) asm volatile("cp.async.wait_group 1;" ::: "memory");
        else                  asm volatile("cp.async.wait_group 0;" ::: "memory");
        __syncthreads();
        if (i + 3 < nch) {
            const uint32_t st = sbase + (uint32_t)((i + 3) & 3) * GS_STG;
            load_op32(st,         Ag, Kdim, (i + 3) << 5, tid);
            load_op32(st + GS_OP, Bg, Kdim, (i + 3) << 5, tid);
            asm volatile("cp.async.commit_group;" ::: "memory");
        }
        const uint32_t sb = sbase + (uint32_t)(i & 3) * GS_STG;

        uint32_t a4[2][4][4], b4[2][4][4];
#pragma unroll
        for (int ks = 0; ks < 2; ks++) {
#pragma unroll
            for (int mt = 0; mt < 4; mt++)
                ldsm4(a4[ks][mt], sb + aoff + (uint32_t)(mt * 1280 + ks * 32));
#pragma unroll
            for (int np = 0; np < 4; np++)
                ldsm4(b4[ks][np], sb + boff + (uint32_t)(np * 1280 + ks * 32));
        }
#pragma unroll
        for (int mt = 0; mt < 4; mt++)
#pragma unroll
            for (int nt = 0; nt < 8; nt++) {
                const int np = nt >> 1, h = (nt & 1) * 2;
                mma_f16(acc[mt][nt], a4[0][mt], b4[0][np][h], b4[0][np][h + 1]);
                mma_f16(acc[mt][nt], a4[1][mt], b4[1][np][h], b4[1][np][h + 1]);
            }
    }

    const int lr4 = lane >> 2;
    const int lc2 = (lane & 3) * 2;

    if (mode == 0) {
        const int nb  = n0 + warp_n * 64;
        const int sec = nb >> 10;
        const int f   = nb & 1023;
        const int h   = f >> 6;
        float gstd = 1.0f, grec = 1.0f;
        if (sec < 2) {
            const float ss = sigmoidf_(skip_std[0]);
            const float sl = sigmoidf_(skip_low[0]);
            gstd = sqrtf(fmaxf(w_std[h] * ss, 1e-8f)) * QK_SCALE;
            grec = sqrtf(fmaxf(w_rec[h] * sl, 1e-8f)) * QK_SCALE;
        }
        __half* dst = (sec == 0) ? g_q16 : (sec == 1) ? g_k16 : g_v16;
#pragma unroll
        for (int mt = 0; mt < 4; mt++) {
            const int r0 = m0 + warp_m * 64 + mt * 16 + lr4;
#pragma unroll
            for (int half = 0; half < 2; half++) {
                const int m = r0 + half * 8;
                const int b = m >> 11;
                const int t = m & (T_ - 1);
                const size_t base = (((size_t)(b * H_ + h)) * T_ + t) * D_;
#pragma unroll
                for (int nt = 0; nt < 8; nt++) {
                    const int d = nt * 8 + lc2;
                    const float s0 = (sec < 2) ? ((d     < DSTD_) ? gstd : grec) : 1.0f;
                    const float s1 = (sec < 2) ? ((d + 1 < DSTD_) ? gstd : grec) : 1.0f;
                    uint32_t hv = packh2_(acc[mt][nt][half*2 + 0] * s0,
                                          acc[mt][nt][half*2 + 1] * s1);
                    *(uint32_t*)&dst[base + d] = hv;
                }
            }
        }
    } else {
#pragma unroll
        for (int mt = 0; mt < 4; mt++) {
            const int r0 = m0 + warp_m * 64 + mt * 16 + lr4;
#pragma unroll
            for (int half = 0; half < 2; half++) {
                const int m = r0 + half * 8;
#pragma unroll
                for (int nt = 0; nt < 8; nt++) {
                    const int col = n0 + warp_n * 64 + nt * 8 + lc2;
                    float2 o;
                    o.x = acc[mt][nt][half * 2 + 0];
                    o.y = acc[mt][nt][half * 2 + 1];
                    *(float2*)&Cout[(size_t)m * Ndim + col] = o;
                }
            }
        }
    }
}

// ---------------------------------------------------------------------------
// fp16 tensor-core causal flash attention + reciprocal mix.
// R11: balanced q-tile pairing FIXED — grid.x = NQT/2 = 8 CTAs; CTA x runs
// heavy tile (NQT-1-x) = 15-x, then light tile (x). Constant 34 KV-rounds
// per CTA, one balanced wave. Conditional (exact) rescale retained.
// ---------------------------------------------------------------------------
#define NQT_    (T_/128)            // 16 q-tiles
#define AQ_B    18432               // Q region: 128*144
#define AT_T    9216                // one 64x144 tile
#define AT_STG2 (2*AT_T)            // K+V stage
#define AT_SMEM (AQ_B + 3*AT_STG2)  // 73728

__device__ __forceinline__ void attn_load_kv16(
    uint32_t sb, int k0, int tid,
    const __half* __restrict__ Kg, const __half* __restrict__ Vg)
{
#pragma unroll
    for (int p = 0; p < 2; p++) {
        int idx = tid + p * 256;    // 0..511
        int row = idx >> 3;         // 0..63
        int c8  = (idx & 7) * 8;
        cp16(sb + (uint32_t)(row * 144 + c8 * 2),        Kg + (size_t)(k0 + row) * 64 + c8);
        cp16(sb + (uint32_t)(AT_T + row * 144 + c8 * 2), Vg + (size_t)(k0 + row) * 64 + c8);
    }
}

__global__ void __launch_bounds__(256, 2) attn_f16_kernel(const float* __restrict__ rwr_alpha)
{
    extern __shared__ char smem[];
    const uint32_t sbase = smem_u32(smem);
    const int tid  = threadIdx.x;
    const int wid  = tid >> 5;
    const int lane = tid & 31;
    const int bh = blockIdx.y;

    const size_t hoff = (size_t)bh * (T_ * D_);
    const __half* Qg = g_q16 + hoff;
    const __half* Kg = g_k16 + hoff;
    const __half* Vg = g_v16 + hoff;

    const int h = bh & (H_ - 1);
    const int b = bh >> 4;
    const float alpha = fminf(fmaxf(rwr_alpha[h], 0.0f), 0.5f);
    const float om = 1.0f - alpha;

    const int lr = lane & 7, sel = lane >> 3;
    const int rowA = ((sel & 1) ? 8 : 0) + lr;
    const int kbA  = (sel & 2) ? 16 : 0;
    const int rowB = ((sel & 2) ? 8 : 0) + lr;
    const int kbB  = (sel & 1) ? 16 : 0;
    const int g  = lane >> 2;
    const int t2 = (lane & 3) * 2;
    const uint32_t ones = 0x3C003C00u;   // all-ones B frag: every col = rowsum

#pragma unroll 1
    for (int seg = 0; seg < 2; seg++) {
        // FIX: heavy tile index is over ALL NQT_ tiles, not gridDim.x.
        // CTA x handles tiles (NQT_-1-x) then (x); together CTAs 0..NQT_/2-1
        // cover all 16 tiles exactly once with equal total work (34 rounds).
        const int qt = (seg == 0) ? (NQT_ - 1 - (int)blockIdx.x)
                                  : (int)blockIdx.x;
        const int q0 = qt * 128;
        const int qw = q0 + wid * 16;
        const int nkt = 2 * qt + 2;

        __syncthreads();   // prior segment fully done before SMEM reuse

        // Q tile load (group 0)
#pragma unroll
        for (int p = 0; p < 4; p++) {
            int idx = tid + p * 256;
            int row = idx >> 3;
            int c8  = (idx & 7) * 8;
            cp16(sbase + (uint32_t)(row * 144 + c8 * 2), Qg + (size_t)(q0 + row) * 64 + c8);
        }
        asm volatile("cp.async.commit_group;" ::: "memory");

        attn_load_kv16(sbase + AQ_B,           0,  tid, Kg, Vg);
        asm volatile("cp.async.commit_group;" ::: "memory");
        attn_load_kv16(sbase + AQ_B + AT_STG2, 64, tid, Kg, Vg);
        asm volatile("cp.async.commit_group;" ::: "memory");

        asm volatile("cp.async.wait_group 2;" ::: "memory");
        __syncthreads();

        uint32_t qh[4][4];
        {
            const uint32_t qaddr = sbase + (uint32_t)((wid * 16 + rowA) * 144 + kbA);
#pragma unroll
            for (int kc = 0; kc < 4; kc++) ldsm4(qh[kc], qaddr + (uint32_t)(kc * 32));
        }

        float O[8][4];
        float Ol[4] = {0.0f, 0.0f, 0.0f, 0.0f};
        float mrow[2] = {-1e30f, -1e30f};
#pragma unroll
        for (int nt = 0; nt < 8; nt++)
#pragma unroll
            for (int c = 0; c < 4; c++) O[nt][c] = 0.0f;

        for (int kt = 0; kt < nkt; kt++) {
            if (kt + 1 < nkt) asm volatile("cp.async.wait_group 1;" ::: "memory");
            else              asm volatile("cp.async.wait_group 0;" ::: "memory");
            __syncthreads();
            if (kt + 2 < nkt) {
                attn_load_kv16(sbase + AQ_B + (uint32_t)((kt + 2) % 3) * AT_STG2,
                               (kt + 2) * 64, tid, Kg, Vg);
                asm volatile("cp.async.commit_group;" ::: "memory");
            }

            const uint32_t sb = sbase + AQ_B + (uint32_t)(kt % 3) * AT_STG2;
            const int k0 = kt * 64;

            if (k0 <= qw + 15) {
                // ---- S = Q.K^T (scores in log2 domain) ----
                float S[8][4];
#pragma unroll
                for (int nt = 0; nt < 8; nt++)
#pragma unroll
                    for (int c = 0; c < 4; c++) S[nt][c] = 0.0f;

#pragma unroll
                for (int np = 0; np < 4; np++) {
                    const uint32_t kb_ = sb + (uint32_t)((np * 16 + rowB) * 144 + kbB);
#pragma unroll
                    for (int kc = 0; kc < 4; kc++) {
                        uint32_t k4[4];
                        ldsm4(k4, kb_ + (uint32_t)(kc * 32));
                        mma_f16(S[2*np],     qh[kc], k4[0], k4[1]);
                        mma_f16(S[2*np + 1], qh[kc], k4[2], k4[3]);
                    }
                }

                // ---- causal mask ----
                if (k0 + 63 > qw) {
#pragma unroll
                    for (int nt = 0; nt < 8; nt++) {
                        const int colb = k0 + nt * 8 + t2;
#pragma unroll
                        for (int c = 0; c < 2; c++) {
                            if (colb + c > qw + g)     S[nt][c]     = -1e30f;
                            if (colb + c > qw + g + 8) S[nt][2 + c] = -1e30f;
                        }
                    }
                }

                // ---- row max + CONDITIONAL rescale ----
                float mn[2];
#pragma unroll
                for (int r = 0; r < 2; r++) {
                    float mx = -1e30f;
#pragma unroll
                    for (int nt = 0; nt < 8; nt++)
                        mx = fmaxf(mx, fmaxf(S[nt][2*r], S[nt][2*r + 1]));
                    mx = fmaxf(mx, __shfl_xor_sync(0xffffffffu, mx, 1));
                    mx = fmaxf(mx, __shfl_xor_sync(0xffffffffu, mx, 2));
                    mn[r] = fmaxf(mrow[r], mx);
                }
                // skip is EXACT when no row max rose (corr == ex2(0) == 1)
                if (__any_sync(0xffffffffu,
                               (mn[0] > mrow[0]) | (mn[1] > mrow[1]))) {
#pragma unroll
                    for (int r = 0; r < 2; r++) {
                        const float corr = ex2_(mrow[r] - mn[r]);
                        mrow[r] = mn[r];
#pragma unroll
                        for (int nt = 0; nt < 8; nt++) {
                            O[nt][2*r]     *= corr;
                            O[nt][2*r + 1] *= corr;
                        }
                        Ol[2*r] *= corr;
                    }
                }

                // ---- P = exp2(S - m) in f16x2 ----
                uint32_t pa[4][4];
#pragma unroll
                for (int kc = 0; kc < 4; kc++) {
                    pa[kc][0] = ex2h2_(packh2_(S[2*kc][0]   - mn[0], S[2*kc][1]   - mn[0]));
                    pa[kc][1] = ex2h2_(packh2_(S[2*kc][2]   - mn[1], S[2*kc][3]   - mn[1]));
                    pa[kc][2] = ex2h2_(packh2_(S[2*kc+1][0] - mn[0], S[2*kc+1][1] - mn[0]));
                    pa[kc][3] = ex2h2_(packh2_(S[2*kc+1][2] - mn[1], S[2*kc+1][3] - mn[1]));
                }

                // ---- O += P.V ; l += P.ones (same P, fp32 accum) ----
#pragma unroll
                for (int kc = 0; kc < 4; kc++) {
                    mma_f16(Ol, pa[kc], ones, ones);
#pragma unroll
                    for (int nd = 0; nd < 4; nd++) {
                        uint32_t v4[4];
                        const uint32_t vaddr = sb + (uint32_t)(AT_T
                            + (kc * 16 + (lane & 15)) * 144
                            + nd * 32 + ((lane & 16) ? 16 : 0));
                        ldsm4t(v4, vaddr);
                        mma_f16(O[2*nd],     pa[kc], v4[0], v4[1]);
                        mma_f16(O[2*nd + 1], pa[kc], v4[2], v4[3]);
                    }
                }
            }
        }

        // ---- epilogue: normalize, reciprocal mix, write y fp16 ----
#pragma unroll
        for (int r = 0; r < 2; r++) {
            const int q = qw + g + r * 8;
            const float inv = 1.0f / Ol[2*r];
            const size_t vrow = (size_t)q * 64;
            const size_t orow = ((size_t)(b * T_ + q)) * C_ + h * 64;
#pragma unroll
            for (int nt = 0; nt < 8; nt++) {
                const int d = nt * 8 + t2;
                const uint32_t uv = *(const uint32_t*)&Vg[vrow + d];
                const float2 fv = __half22float2(*(const __half2*)&uv);
                const float y0 = om * (O[nt][2*r]     * inv) + alpha * fv.x;
                const float y1 = om * (O[nt][2*r + 1] * inv) + alpha * fv.y;
                *(uint32_t*)&g_y16[orow + d] = packh2_(y0, y1);
            }
        }
    }
}

// ---------------------------------------------------------------------------
extern "C" void kernel_launch(void* const* d_in, const int* in_sizes, int n_in,
                              void* d_out, int out_size)
{
    const float* x         = (const float*)d_in[0];
    const float* W_attn    = (const float*)d_in[1];
    const float* W_proj    = (const float*)d_in[2];
    const float* w_std     = (const float*)d_in[3];
    const float* w_rec     = (const float*)d_in[4];
    const float* skip_std  = (const float*)d_in[5];
    const float* skip_low  = (const float*)d_in[6];
    const float* rwr_alpha = (const float*)d_in[7];
    float* out = (float*)d_out;

    static void *p_x16 = nullptr, *p_wa16, *p_wp16, *p_y16;
    if (!p_x16) {
        cudaGetSymbolAddress(&p_x16,  g_x16);
        cudaGetSymbolAddress(&p_wa16, g_wa16);
        cudaGetSymbolAddress(&p_wp16, g_wp16);
        cudaGetSymbolAddress(&p_y16,  g_y16);
    }

    static bool attr_set = false;
    if (!attr_set) {
        cudaFuncSetAttribute(gemm_f16_kernel, cudaFuncAttributeMaxDynamicSharedMemorySize, GS_SMEM);
        cudaFuncSetAttribute(attn_f16_kernel, cudaFuncAttributeMaxDynamicSharedMemorySize, AT_SMEM);
        attr_set = true;
    }

    // 1. fused fp32 -> fp16 conversion (x, W_attn, W_proj)
    conv_kernel<<<(NTOT4_ + 255) / 256, 256>>>(
        (const float4*)x, (const float4*)W_attn, (const float4*)W_proj);

    // 2. QKV GEMM -> q/k/v fp16 with head scaling (+ log2e fold for q,k)
    gemm_f16_kernel<<<dim3(3*C_/128, M_/128), 128, GS_SMEM>>>(
        (const __half*)p_x16, (const __half*)p_wa16,
        nullptr, 3*C_, C_, 0, w_std, w_rec, skip_std, skip_low);

    // 3. attention: NQT_/2 = 8 CTAs per head, each a balanced (heavy, light)
    //    q-tile pair -> 256 CTAs total, one balanced wave
    attn_f16_kernel<<<dim3(NQT_/2, B_*H_), 256, AT_SMEM>>>(rwr_alpha);

    // 4. output projection -> fp32 out
    gemm_f16_kernel<<<dim3(C_/128, M_/128), 128, GS_SMEM>>>(
        (const __half*)p_y16, (const __half*)p_wp16,
        out, C_, C_, 1, nullptr, nullptr, nullptr, nullptr);
}

// round 13
// speedup vs baseline: 9.7564x; 1.0155x over previous
#include <cuda_runtime.h>
#include <cuda_fp16.h>
#include <cstdint>
#include <math.h>

// Problem constants
#define B_    2
#define T_    2048
#define C_    1024
#define H_    16
#define D_    64
#define DSTD_ 60
#define M_    (B_*T_)   // 4096 rows

// ---------------------------------------------------------------------------
// Scratch (__device__ globals; no allocation allowed)
// ---------------------------------------------------------------------------
__device__ __half g_x16[M_*C_];
__device__ __half g_wa16[3*C_*C_];
__device__ __half g_wp16[C_*C_];
__device__ __half g_y16[M_*C_];
__device__ __half g_q16[B_*H_*T_*D_];   // [B*H, T, D]
__device__ __half g_k16[B_*H_*T_*D_];
__device__ __half g_v16[B_*H_*T_*D_];
__device__ int    g_ctr;                // attention work-queue counter

__device__ __forceinline__ float sigmoidf_(float v) { return 1.0f / (1.0f + __expf(-v)); }

__device__ __forceinline__ uint32_t smem_u32(const void* p) {
    return (uint32_t)__cvta_generic_to_shared(p);
}

__device__ __forceinline__ float ex2_(float x) {
    float r; asm("ex2.approx.f32 %0, %1;" : "=f"(r) : "f"(x)); return r;
}
__device__ __forceinline__ uint32_t ex2h2_(uint32_t x) {
    uint32_t r; asm("ex2.approx.f16x2 %0, %1;" : "=r"(r) : "r"(x)); return r;
}
__device__ __forceinline__ uint32_t packh2_(float x, float y) {
    __half2 h = __floats2half2_rn(x, y);
    return *reinterpret_cast<uint32_t*>(&h);
}

// ---------------------------------------------------------------------------
// warp-mma helpers (baseline PTX ISA — safe for compute_103 target)
// ---------------------------------------------------------------------------
__device__ __forceinline__ void ldsm4(uint32_t* r, uint32_t addr) {
    asm volatile("ldmatrix.sync.aligned.m8n8.x4.shared.b16 {%0,%1,%2,%3}, [%4];"
        : "=r"(r[0]), "=r"(r[1]), "=r"(r[2]), "=r"(r[3]) : "r"(addr));
}

__device__ __forceinline__ void ldsm4t(uint32_t* r, uint32_t addr) {
    asm volatile("ldmatrix.sync.aligned.m8n8.x4.trans.shared.b16 {%0,%1,%2,%3}, [%4];"
        : "=r"(r[0]), "=r"(r[1]), "=r"(r[2]), "=r"(r[3]) : "r"(addr));
}

__device__ __forceinline__ void mma_f16(float* c, const uint32_t* a, uint32_t b0, uint32_t b1) {
    asm volatile("mma.sync.aligned.m16n8k16.row.col.f32.f16.f16.f32 "
        "{%0,%1,%2,%3}, {%4,%5,%6,%7}, {%8,%9}, {%0,%1,%2,%3};"
        : "+f"(c[0]), "+f"(c[1]), "+f"(c[2]), "+f"(c[3])
        : "r"(a[0]), "r"(a[1]), "r"(a[2]), "r"(a[3]), "r"(b0), "r"(b1));
}

__device__ __forceinline__ void cp16(uint32_t saddr, const void* gaddr) {
    asm volatile("cp.async.cg.shared.global [%0], [%1], 16;" :: "r"(saddr), "l"(gaddr));
}

// ---------------------------------------------------------------------------
// fused fp32 -> fp16 convert for x, W_attn, W_proj (one launch)
// ---------------------------------------------------------------------------
#define NX4_  (M_*C_/4)       // 1048576
#define NWA4_ (3*C_*C_/4)     // 786432
#define NWP4_ (C_*C_/4)       // 262144
#define NTOT4_ (NX4_+NWA4_+NWP4_)

__global__ __launch_bounds__(256) void conv_kernel(
    const float4* __restrict__ x, const float4* __restrict__ wa, const float4* __restrict__ wp)
{
    int i = blockIdx.x * blockDim.x + threadIdx.x;
    if (i >= NTOT4_) return;
    const float4* s; uint2* d; int o;
    if (i < NX4_)              { s = x;  d = (uint2*)g_x16;  o = i; }
    else if (i < NX4_ + NWA4_) { s = wa; d = (uint2*)g_wa16; o = i - NX4_; }
    else                       { s = wp; d = (uint2*)g_wp16; o = i - NX4_ - NWA4_; }
    float4 v = s[o];
    d[o] = make_uint2(packh2_(v.x, v.y), packh2_(v.z, v.w));
}

// ---------------------------------------------------------------------------
// fp16 warp-MMA GEMM (NT) — unchanged from R9 (acc-major, BK=32, 4-stage).
// ---------------------------------------------------------------------------
#define GS_OP   10240          // 128 rows * 80 B
#define GS_STG  (2*GS_OP)      // 20480 (A + B)
#define GS_SMEM (4*GS_STG)     // 81920

// scale const: D^-1/4 * sqrt(log2(e))
#define QK_SCALE 0.42466089786070306f

__device__ __forceinline__ void load_op32(
    uint32_t sdst, const __half* __restrict__ src, int Kdim, int k0, int tid)
{
#pragma unroll
    for (int p = 0; p < 4; p++) {
        int idx = tid + p * 128;        // 0..511
        int row = idx >> 2;             // 0..127
        int c8  = (idx & 3) * 8;        // half col 0..24
        cp16(sdst + (uint32_t)(row * 80 + c8 * 2), src + (size_t)row * Kdim + k0 + c8);
    }
}

__global__ void __launch_bounds__(128, 2) gemm_f16_kernel(
    const __half* __restrict__ A, const __half* __restrict__ Bm,
    float* __restrict__ Cout, int Ndim, int Kdim, int mode,
    const float* __restrict__ w_std, const float* __restrict__ w_rec,
    const float* __restrict__ skip_std, const float* __restrict__ skip_low)
{
    extern __shared__ char smem[];
    const uint32_t sbase = smem_u32(smem);
    const int tid  = threadIdx.x;
    const int wid  = tid >> 5;
    const int lane = tid & 31;
    const int warp_m = wid >> 1;        // 0..1
    const int warp_n = wid & 1;         // 0..1

    const int m0 = blockIdx.y * 128;
    const int n0 = blockIdx.x * 128;

    const int lr = lane & 7, sel = lane >> 3;
    const int rowA = ((sel & 1) ? 8 : 0) + lr;
    const int kbA  = (sel & 2) ? 16 : 0;
    const int rowB = ((sel & 2) ? 8 : 0) + lr;
    const int kbB  = (sel & 1) ? 16 : 0;

    const uint32_t aoff = (uint32_t)((warp_m * 64 + rowA) * 80 + kbA);
    const uint32_t boff = (uint32_t)(GS_OP + (warp_n * 64 + rowB) * 80 + kbB);

    const __half* Ag = A  + (size_t)m0 * Kdim;
    const __half* Bg = Bm + (size_t)n0 * Kdim;

    float acc[4][8][4];
#pragma unroll
    for (int a = 0; a < 4; a++)
#pragma unroll
        for (int b = 0; b < 8; b++)
#pragma unroll
            for (int c = 0; c < 4; c++) acc[a][b][c] = 0.0f;

    const int nch = Kdim >> 5;          // BK=32

#pragma unroll
    for (int pc = 0; pc < 3; pc++) {
        const uint32_t st = sbase + (uint32_t)pc * GS_STG;
        load_op32(st,         Ag, Kdim, pc << 5, tid);
        load_op32(st + GS_OP, Bg, Kdim, pc << 5, tid);
        asm volatile("cp.async.commit_group;" ::: "memory");
    }

    for (int i = 0; i < nch; i++) {
        if (i + 2 < nch)      asm volatile("cp.async.wait_group 2;" ::: "memory");
        else if (i + 1 < nch) asm volatile("cp.async.wait_group 1;" ::: "memory");
        else                  asm volatile("cp.async.wait_group 0;" ::: "memory");
        __syncthreads();
        if (i + 3 < nch) {
            const uint32_t st = sbase + (uint32_t)((i + 3) & 3) * GS_STG;
            load_op32(st,         Ag, Kdim, (i + 3) << 5, tid);
            load_op32(st + GS_OP, Bg, Kdim, (i + 3) << 5, tid);
            asm volatile("cp.async.commit_group;" ::: "memory");
        }
        const uint32_t sb = sbase + (uint32_t)(i & 3) * GS_STG;

        uint32_t a4[2][4][4], b4[2][4][4];
#pragma unroll
        for (int ks = 0; ks < 2; ks++) {
#pragma unroll
            for (int mt = 0; mt < 4; mt++)
                ldsm4(a4[ks][mt], sb + aoff + (uint32_t)(mt * 1280 + ks * 32));
#pragma unroll
            for (int np = 0; np < 4; np++)
                ldsm4(b4[ks][np], sb + boff + (uint32_t)(np * 1280 + ks * 32));
        }
#pragma unroll
        for (int mt = 0; mt < 4; mt++)
#pragma unroll
            for (int nt = 0; nt < 8; nt++) {
                const int np = nt >> 1, h = (nt & 1) * 2;
                mma_f16(acc[mt][nt], a4[0][mt], b4[0][np][h], b4[0][np][h + 1]);
                mma_f16(acc[mt][nt], a4[1][mt], b4[1][np][h], b4[1][np][h + 1]);
            }
    }

    const int lr4 = lane >> 2;
    const int lc2 = (lane & 3) * 2;

    if (mode == 0) {
        const int nb  = n0 + warp_n * 64;
        const int sec = nb >> 10;
        const int f   = nb & 1023;
        const int h   = f >> 6;
        float gstd = 1.0f, grec = 1.0f;
        if (sec < 2) {
            const float ss = sigmoidf_(skip_std[0]);
            const float sl = sigmoidf_(skip_low[0]);
            gstd = sqrtf(fmaxf(w_std[h] * ss, 1e-8f)) * QK_SCALE;
            grec = sqrtf(fmaxf(w_rec[h] * sl, 1e-8f)) * QK_SCALE;
        }
        __half* dst = (sec == 0) ? g_q16 : (sec == 1) ? g_k16 : g_v16;
#pragma unroll
        for (int mt = 0; mt < 4; mt++) {
            const int r0 = m0 + warp_m * 64 + mt * 16 + lr4;
#pragma unroll
            for (int half = 0; half < 2; half++) {
                const int m = r0 + half * 8;
                const int b = m >> 11;
                const int t = m & (T_ - 1);
                const size_t base = (((size_t)(b * H_ + h)) * T_ + t) * D_;
#pragma unroll
                for (int nt = 0; nt < 8; nt++) {
                    const int d = nt * 8 + lc2;
                    const float s0 = (sec < 2) ? ((d     < DSTD_) ? gstd : grec) : 1.0f;
                    const float s1 = (sec < 2) ? ((d + 1 < DSTD_) ? gstd : grec) : 1.0f;
                    uint32_t hv = packh2_(acc[mt][nt][half*2 + 0] * s0,
                                          acc[mt][nt][half*2 + 1] * s1);
                    *(uint32_t*)&dst[base + d] = hv;
                }
            }
        }
    } else {
#pragma unroll
        for (int mt = 0; mt < 4; mt++) {
            const int r0 = m0 + warp_m * 64 + mt * 16 + lr4;
#pragma unroll
            for (int half = 0; half < 2; half++) {
                const int m = r0 + half * 8;
#pragma unroll
                for (int nt = 0; nt < 8; nt++) {
                    const int col = n0 + warp_n * 64 + nt * 8 + lc2;
                    float2 o;
                    o.x = acc[mt][nt][half * 2 + 0];
                    o.y = acc[mt][nt][half * 2 + 1];
                    *(float2*)&Cout[(size_t)m * Ndim + col] = o;
                }
            }
        }
    }
}

// ---------------------------------------------------------------------------
// fp16 tensor-core causal flash attention + reciprocal mix.
// R13: DYNAMIC WORK QUEUE — persistent grid of 296 CTAs (2/SM) pops q-tiles
// heavy-first from a global atomic counter (idx -> qt = 15 - idx/32,
// bh = idx%32). Every SM drains ~8704/148 = 59 rounds vs 68 for the static
// 256-CTA grid. Output is bit-deterministic (tile->output map fixed).
// Conditional (exact) rescale retained.
// ---------------------------------------------------------------------------
#define NQT_    (T_/128)            // 16 q-tiles
#define NTILE_  (NQT_*B_*H_)        // 512 work items
#define AQ_B    18432               // Q region: 128*144
#define AT_T    9216                // one 64x144 tile
#define AT_STG2 (2*AT_T)            // K+V stage
#define AT_SMEM (AQ_B + 3*AT_STG2)  // 73728

__device__ __forceinline__ void attn_load_kv16(
    uint32_t sb, int k0, int tid,
    const __half* __restrict__ Kg, const __half* __restrict__ Vg)
{
#pragma unroll
    for (int p = 0; p < 2; p++) {
        int idx = tid + p * 256;    // 0..511
        int row = idx >> 3;         // 0..63
        int c8  = (idx & 7) * 8;
        cp16(sb + (uint32_t)(row * 144 + c8 * 2),        Kg + (size_t)(k0 + row) * 64 + c8);
        cp16(sb + (uint32_t)(AT_T + row * 144 + c8 * 2), Vg + (size_t)(k0 + row) * 64 + c8);
    }
}

__global__ void __launch_bounds__(256, 2) attn_f16_kernel(const float* __restrict__ rwr_alpha)
{
    extern __shared__ char smem[];
    __shared__ int s_tile;
    const uint32_t sbase = smem_u32(smem);
    const int tid  = threadIdx.x;
    const int wid  = tid >> 5;
    const int lane = tid & 31;

    const int lr = lane & 7, sel = lane >> 3;
    const int rowA = ((sel & 1) ? 8 : 0) + lr;
    const int kbA  = (sel & 2) ? 16 : 0;
    const int rowB = ((sel & 2) ? 8 : 0) + lr;
    const int kbB  = (sel & 1) ? 16 : 0;
    const int g  = lane >> 2;
    const int t2 = (lane & 3) * 2;
    const uint32_t ones = 0x3C003C00u;   // all-ones B frag: every col = rowsum

    for (;;) {
        __syncthreads();                 // prior tile fully done; s_tile free
        if (tid == 0) s_tile = atomicAdd(&g_ctr, 1);
        __syncthreads();
        const int idx = s_tile;
        if (idx >= NTILE_) break;

        // heavy-first: all 32 heads' qt=15 tiles, then qt=14, ...
        const int qt = (NQT_ - 1) - (idx >> 5);
        const int bh = idx & 31;
        const int q0 = qt * 128;
        const int qw = q0 + wid * 16;
        const int nkt = 2 * qt + 2;

        const size_t hoff = (size_t)bh * (T_ * D_);
        const __half* Qg = g_q16 + hoff;
        const __half* Kg = g_k16 + hoff;
        const __half* Vg = g_v16 + hoff;

        const int h = bh & (H_ - 1);
        const int b = bh >> 4;
        const float alpha = fminf(fmaxf(rwr_alpha[h], 0.0f), 0.5f);
        const float om = 1.0f - alpha;

        // Q tile load (group 0)
#pragma unroll
        for (int p = 0; p < 4; p++) {
            int i2 = tid + p * 256;
            int row = i2 >> 3;
            int c8  = (i2 & 7) * 8;
            cp16(sbase + (uint32_t)(row * 144 + c8 * 2), Qg + (size_t)(q0 + row) * 64 + c8);
        }
        asm volatile("cp.async.commit_group;" ::: "memory");

        attn_load_kv16(sbase + AQ_B,           0,  tid, Kg, Vg);
        asm volatile("cp.async.commit_group;" ::: "memory");
        attn_load_kv16(sbase + AQ_B + AT_STG2, 64, tid, Kg, Vg);
        asm volatile("cp.async.commit_group;" ::: "memory");

        asm volatile("cp.async.wait_group 2;" ::: "memory");
        __syncthreads();

        uint32_t qh[4][4];
        {
            const uint32_t qaddr = sbase + (uint32_t)((wid * 16 + rowA) * 144 + kbA);
#pragma unroll
            for (int kc = 0; kc < 4; kc++) ldsm4(qh[kc], qaddr + (uint32_t)(kc * 32));
        }

        float O[8][4];
        float Ol[4] = {0.0f, 0.0f, 0.0f, 0.0f};
        float mrow[2] = {-1e30f, -1e30f};
#pragma unroll
        for (int nt = 0; nt < 8; nt++)
#pragma unroll
            for (int c = 0; c < 4; c++) O[nt][c] = 0.0f;

        for (int kt = 0; kt < nkt; kt++) {
            if (kt + 1 < nkt) asm volatile("cp.async.wait_group 1;" ::: "memory");
            else              asm volatile("cp.async.wait_group 0;" ::: "memory");
            __syncthreads();
            if (kt + 2 < nkt) {
                attn_load_kv16(sbase + AQ_B + (uint32_t)((kt + 2) % 3) * AT_STG2,
                               (kt + 2) * 64, tid, Kg, Vg);
                asm volatile("cp.async.commit_group;" ::: "memory");
            }

            const uint32_t sb = sbase + AQ_B + (uint32_t)(kt % 3) * AT_STG2;
            const int k0 = kt * 64;

            if (k0 <= qw + 15) {
                // ---- S = Q.K^T (scores in log2 domain) ----
                float S[8][4];
#pragma unroll
                for (int nt = 0; nt < 8; nt++)
#pragma unroll
                    for (int c = 0; c < 4; c++) S[nt][c] = 0.0f;

#pragma unroll
                for (int np = 0; np < 4; np++) {
                    const uint32_t kb_ = sb + (uint32_t)((np * 16 + rowB) * 144 + kbB);
#pragma unroll
                    for (int kc = 0; kc < 4; kc++) {
                        uint32_t k4[4];
                        ldsm4(k4, kb_ + (uint32_t)(kc * 32));
                        mma_f16(S[2*np],     qh[kc], k4[0], k4[1]);
                        mma_f16(S[2*np + 1], qh[kc], k4[2], k4[3]);
                    }
                }

                // ---- causal mask ----
                if (k0 + 63 > qw) {
#pragma unroll
                    for (int nt = 0; nt < 8; nt++) {
                        const int colb = k0 + nt * 8 + t2;
#pragma unroll
                        for (int c = 0; c < 2; c++) {
                            if (colb + c > qw + g)     S[nt][c]     = -1e30f;
                            if (colb + c > qw + g + 8) S[nt][2 + c] = -1e30f;
                        }
                    }
                }

                // ---- row max + CONDITIONAL rescale ----
                float mn[2];
#pragma unroll
                for (int r = 0; r < 2; r++) {
                    float mx = -1e30f;
#pragma unroll
                    for (int nt = 0; nt < 8; nt++)
                        mx = fmaxf(mx, fmaxf(S[nt][2*r], S[nt][2*r + 1]));
                    mx = fmaxf(mx, __shfl_xor_sync(0xffffffffu, mx, 1));
                    mx = fmaxf(mx, __shfl_xor_sync(0xffffffffu, mx, 2));
                    mn[r] = fmaxf(mrow[r], mx);
                }
                // skip is EXACT when no row max rose (corr == ex2(0) == 1)
                if (__any_sync(0xffffffffu,
                               (mn[0] > mrow[0]) | (mn[1] > mrow[1]))) {
#pragma unroll
                    for (int r = 0; r < 2; r++) {
                        const float corr = ex2_(mrow[r] - mn[r]);
                        mrow[r] = mn[r];
#pragma unroll
                        for (int nt = 0; nt < 8; nt++) {
                            O[nt][2*r]     *= corr;
                            O[nt][2*r + 1] *= corr;
                        }
                        Ol[2*r] *= corr;
                    }
                }

                // ---- P = exp2(S - m) in f16x2 ----
                uint32_t pa[4][4];
#pragma unroll
                for (int kc = 0; kc < 4; kc++) {
                    pa[kc][0] = ex2h2_(packh2_(S[2*kc][0]   - mn[0], S[2*kc][1]   - mn[0]));
                    pa[kc][1] = ex2h2_(packh2_(S[2*kc][2]   - mn[1], S[2*kc][3]   - mn[1]));
                    pa[kc][2] = ex2h2_(packh2_(S[2*kc+1][0] - mn[0], S[2*kc+1][1] - mn[0]));
                    pa[kc][3] = ex2h2_(packh2_(S[2*kc+1][2] - mn[1], S[2*kc+1][3] - mn[1]));
                }

                // ---- O += P.V ; l += P.ones (same P, fp32 accum) ----
#pragma unroll
                for (int kc = 0; kc < 4; kc++) {
                    mma_f16(Ol, pa[kc], ones, ones);
#pragma unroll
                    for (int nd = 0; nd < 4; nd++) {
                        uint32_t v4[4];
                        const uint32_t vaddr = sb + (uint32_t)(AT_T
                            + (kc * 16 + (lane & 15)) * 144
                            + nd * 32 + ((lane & 16) ? 16 : 0));
                        ldsm4t(v4, vaddr);
                        mma_f16(O[2*nd],     pa[kc], v4[0], v4[1]);
                        mma_f16(O[2*nd + 1], pa[kc], v4[2], v4[3]);
                    }
                }
            }
        }

        // ---- epilogue: normalize, reciprocal mix, write y fp16 ----
#pragma unroll
        for (int r = 0; r < 2; r++) {
            const int q = qw + g + r * 8;
            const float inv = 1.0f / Ol[2*r];
            const size_t vrow = (size_t)q * 64;
            const size_t orow = ((size_t)(b * T_ + q)) * C_ + h * 64;
#pragma unroll
            for (int nt = 0; nt < 8; nt++) {
                const int d = nt * 8 + t2;
                const uint32_t uv = *(const uint32_t*)&Vg[vrow + d];
                const float2 fv = __half22float2(*(const __half2*)&uv);
                const float y0 = om * (O[nt][2*r]     * inv) + alpha * fv.x;
                const float y1 = om * (O[nt][2*r + 1] * inv) + alpha * fv.y;
                *(uint32_t*)&g_y16[orow + d] = packh2_(y0, y1);
            }
        }
    }
}

// ---------------------------------------------------------------------------
extern "C" void kernel_launch(void* const* d_in, const int* in_sizes, int n_in,
                              void* d_out, int out_size)
{
    const float* x         = (const float*)d_in[0];
    const float* W_attn    = (const float*)d_in[1];
    const float* W_proj    = (const float*)d_in[2];
    const float* w_std     = (const float*)d_in[3];
    const float* w_rec     = (const float*)d_in[4];
    const float* skip_std  = (const float*)d_in[5];
    const float* skip_low  = (const float*)d_in[6];
    const float* rwr_alpha = (const float*)d_in[7];
    float* out = (float*)d_out;

    static void *p_x16 = nullptr, *p_wa16, *p_wp16, *p_y16, *p_ctr;
    if (!p_x16) {
        cudaGetSymbolAddress(&p_x16,  g_x16);
        cudaGetSymbolAddress(&p_wa16, g_wa16);
        cudaGetSymbolAddress(&p_wp16, g_wp16);
        cudaGetSymbolAddress(&p_y16,  g_y16);
        cudaGetSymbolAddress(&p_ctr,  g_ctr);
    }

    static bool attr_set = false;
    if (!attr_set) {
        cudaFuncSetAttribute(gemm_f16_kernel, cudaFuncAttributeMaxDynamicSharedMemorySize, GS_SMEM);
        cudaFuncSetAttribute(attn_f16_kernel, cudaFuncAttributeMaxDynamicSharedMemorySize, AT_SMEM);
        attr_set = true;
    }

    // 1. fused fp32 -> fp16 conversion (x, W_attn, W_proj)
    conv_kernel<<<(NTOT4_ + 255) / 256, 256>>>(
        (const float4*)x, (const float4*)W_attn, (const float4*)W_proj);

    // 2. QKV GEMM -> q/k/v fp16 with head scaling (+ log2e fold for q,k)
    gemm_f16_kernel<<<dim3(3*C_/128, M_/128), 128, GS_SMEM>>>(
        (const __half*)p_x16, (const __half*)p_wa16,
        nullptr, 3*C_, C_, 0, w_std, w_rec, skip_std, skip_low);

    // 3. attention: persistent 296-CTA grid, heavy-first atomic work queue
    cudaMemsetAsync(p_ctr, 0, sizeof(int));
    attn_f16_kernel<<<296, 256, AT_SMEM>>>(rwr_alpha);

    // 4. output projection -> fp32 out
    gemm_f16_kernel<<<dim3(C_/128, M_/128), 128, GS_SMEM>>>(
        (const __half*)p_y16, (const __half*)p_wp16,
        out, C_, C_, 1, nullptr, nullptr, nullptr, nullptr);
}